// round 1
// baseline (speedup 1.0000x reference)
#include <cuda_runtime.h>
#include <math.h>

// ---------------- problem constants ----------------
#define BATCH 2
#define TT 8
#define HH 128
#define WW 128
#define CC 192
#define TOKENS (BATCH*TT*HH*WW)          // 262144
#define NWIN 2048                        // 2*4*16*16
#define NWTOK 128                        // tokens per window
#define HEADS 6
#define HDIM 32
#define HIDDEN 768
#define QKVDIM 576
#define ATTSCALE 0.17677669529663687f    // 1/sqrt(32)

// ---------------- scratch (device globals; no allocations allowed) ---------
__device__ float g_xw[(size_t)TOKENS * CC];        // LN1(windowed) / LN2 output
__device__ float g_qkv[(size_t)NWIN * NWTOK * QKVDIM];
__device__ float g_attnout[(size_t)TOKENS * CC];
__device__ float g_x2[(size_t)TOKENS * CC];        // x + attn branch
__device__ float g_h1[(size_t)TOKENS * HIDDEN];

// ---------------- LayerNorm (warp per token), optional window scatter ------
__global__ void ln_kernel(const float* __restrict__ in,
                          const float* __restrict__ g,
                          const float* __restrict__ b,
                          float* __restrict__ out,
                          int windowed)
{
    int token = (blockIdx.x << 3) + (threadIdx.x >> 5);
    int lane  = threadIdx.x & 31;
    size_t base = (size_t)token * CC;

    float v[6];
    float s = 0.f;
    #pragma unroll
    for (int j = 0; j < 6; ++j) { v[j] = in[base + lane + 32*j]; s += v[j]; }
    #pragma unroll
    for (int o = 16; o; o >>= 1) s += __shfl_xor_sync(0xffffffffu, s, o);
    float mu = s * (1.0f / 192.0f);

    float vs = 0.f;
    #pragma unroll
    for (int j = 0; j < 6; ++j) { float d = v[j] - mu; vs += d*d; }
    #pragma unroll
    for (int o = 16; o; o >>= 1) vs += __shfl_xor_sync(0xffffffffu, vs, o);
    float rinv = rsqrtf(vs * (1.0f / 192.0f) + 1e-5f);

    size_t obase;
    if (windowed) {
        int w = token & 127;
        int h = (token >> 7) & 127;
        int t = (token >> 14) & 7;
        int bb = token >> 17;
        int win = ((bb*4 + (t >> 1))*16 + (h >> 3))*16 + (w >> 3);
        int n   = ((t & 1) << 6) | ((h & 7) << 3) | (w & 7);
        obase = ((size_t)win * NWTOK + n) * CC;
    } else {
        obase = base;
    }
    #pragma unroll
    for (int j = 0; j < 6; ++j) {
        int c = lane + 32*j;
        out[obase + c] = (v[j] - mu) * rinv * g[c] + b[c];
    }
}

// ---------------- generic GEMM: out[M,N] = A[M,K] @ W[N,K]^T + bias --------
// mode 0: bias               -> out (row-major M x N)
// mode 1: bias + exact GELU  -> out
// mode 2: bias + resid[m,n]  -> out
// mode 3: bias + window-reverse scatter + resid (token layout), N == CC
#define BM 64
#define BN 64
#define BK 16

__device__ __forceinline__ float gelu_exact(float x) {
    return 0.5f * x * (1.0f + erff(x * 0.70710678118654752f));
}

__global__ __launch_bounds__(256)
void gemm_kernel(const float* __restrict__ A, const float* __restrict__ W,
                 const float* __restrict__ bias, float* __restrict__ out,
                 int M, int N, int K, int mode, const float* __restrict__ resid)
{
    __shared__ float As[BK][68];
    __shared__ float Bs[BK][68];

    int tid  = threadIdx.x;
    int row0 = blockIdx.x * BM;
    int col0 = blockIdx.y * BN;
    int lr = tid >> 2;            // 0..63
    int lc = (tid & 3) << 2;      // 0,4,8,12
    int tm = (tid >> 4) << 2;     // 0..60
    int tn = (tid & 15) << 2;     // 0..60

    const float* Aptr = A + (size_t)(row0 + lr) * K + lc;
    const float* Wptr = W + (size_t)(col0 + lr) * K + lc;

    float acc[4][4] = {};

    for (int kt = 0; kt < K; kt += BK) {
        float4 a4 = *(const float4*)(Aptr + kt);
        float4 b4 = *(const float4*)(Wptr + kt);
        As[lc+0][lr] = a4.x; As[lc+1][lr] = a4.y; As[lc+2][lr] = a4.z; As[lc+3][lr] = a4.w;
        Bs[lc+0][lr] = b4.x; Bs[lc+1][lr] = b4.y; Bs[lc+2][lr] = b4.z; Bs[lc+3][lr] = b4.w;
        __syncthreads();
        #pragma unroll
        for (int kk = 0; kk < BK; ++kk) {
            float4 av = *(const float4*)&As[kk][tm];
            float4 bv = *(const float4*)&Bs[kk][tn];
            acc[0][0] += av.x*bv.x; acc[0][1] += av.x*bv.y; acc[0][2] += av.x*bv.z; acc[0][3] += av.x*bv.w;
            acc[1][0] += av.y*bv.x; acc[1][1] += av.y*bv.y; acc[1][2] += av.y*bv.z; acc[1][3] += av.y*bv.w;
            acc[2][0] += av.z*bv.x; acc[2][1] += av.z*bv.y; acc[2][2] += av.z*bv.z; acc[2][3] += av.z*bv.w;
            acc[3][0] += av.w*bv.x; acc[3][1] += av.w*bv.y; acc[3][2] += av.w*bv.z; acc[3][3] += av.w*bv.w;
        }
        __syncthreads();
    }

    #pragma unroll
    for (int i = 0; i < 4; ++i) {
        int gm = row0 + tm + i;
        // window-reverse token for mode 3
        int token = 0;
        if (mode == 3) {
            int win = gm >> 7, n = gm & 127;
            int bb  = win >> 10;
            int rem = win & 1023;
            int tt  = rem >> 8;
            int hh  = (rem >> 4) & 15;
            int wi  = rem & 15;
            int t = tt*2 + (n >> 6);
            int h = hh*8 + ((n >> 3) & 7);
            int w = wi*8 + (n & 7);
            token = ((bb*TT + t)*HH + h)*WW + w;
        }
        #pragma unroll
        for (int j = 0; j < 4; ++j) {
            int gn = col0 + tn + j;
            float v = acc[i][j] + bias[gn];
            if (mode == 0) {
                out[(size_t)gm * N + gn] = v;
            } else if (mode == 1) {
                out[(size_t)gm * N + gn] = gelu_exact(v);
            } else if (mode == 2) {
                size_t idx = (size_t)gm * N + gn;
                out[idx] = v + resid[idx];
            } else {
                size_t idx = (size_t)token * CC + gn;
                out[idx] = v + resid[idx];
            }
        }
    }
}

// ---------------- attention: one block per (window, head) ------------------
// smem: K (128x36), V (128x36), S (128x129)  = 102912 bytes
#define KP 36
#define SP 129
#define ATTN_SMEM ((2*128*KP + 128*SP) * 4)

__global__ __launch_bounds__(128)
void attn_kernel(const float* __restrict__ qkv,
                 const float* __restrict__ bias_table,
                 float* __restrict__ outbuf)
{
    extern __shared__ float smem[];
    float* ks = smem;                  // 128*36
    float* vs = smem + 128*KP;         // 128*36
    float* S  = smem + 2*128*KP;       // 128*129

    int head = blockIdx.x;
    int win  = blockIdx.y;
    int tid  = threadIdx.x;

    size_t base = (size_t)win * (NWTOK * QKVDIM);
    int qo = head * HDIM;
    int ko = CC   + head * HDIM;
    int vo = 2*CC + head * HDIM;

    for (int idx = tid; idx < NWTOK*HDIM; idx += 128) {
        int r = idx >> 5, c = idx & 31;
        ks[r*KP + c] = qkv[base + (size_t)r*QKVDIM + ko + c];
        vs[r*KP + c] = qkv[base + (size_t)r*QKVDIM + vo + c];
    }

    float qr[HDIM];
    {
        const float* qp = qkv + base + (size_t)tid*QKVDIM + qo;
        #pragma unroll
        for (int d = 0; d < HDIM; ++d) qr[d] = qp[d] * ATTSCALE;
    }
    __syncthreads();

    int t1 = tid >> 6, h1 = (tid >> 3) & 7, w1 = tid & 7;

    float mx = -1e30f;
    for (int m = 0; m < NWTOK; ++m) {
        const float4* kp = (const float4*)(ks + m*KP);
        float dot = 0.f;
        #pragma unroll
        for (int d4 = 0; d4 < 8; ++d4) {
            float4 kv = kp[d4];
            dot += qr[d4*4+0]*kv.x + qr[d4*4+1]*kv.y + qr[d4*4+2]*kv.z + qr[d4*4+3]*kv.w;
        }
        int t2 = m >> 6, h2 = (m >> 3) & 7, w2 = m & 7;
        int bi = (t1 - t2 + 1)*225 + (h1 - h2 + 7)*15 + (w1 - w2 + 7);
        dot += __ldg(bias_table + bi*HEADS + head);
        S[tid*SP + m] = dot;
        mx = fmaxf(mx, dot);
    }

    float sum = 0.f;
    for (int m = 0; m < NWTOK; ++m) {
        float e = __expf(S[tid*SP + m] - mx);
        S[tid*SP + m] = e;
        sum += e;
    }
    float inv = 1.0f / sum;

    float acc[HDIM] = {};
    for (int m = 0; m < NWTOK; ++m) {
        float sm = S[tid*SP + m];
        const float4* vp = (const float4*)(vs + m*KP);
        #pragma unroll
        for (int d4 = 0; d4 < 8; ++d4) {
            float4 vv = vp[d4];
            acc[d4*4+0] += sm*vv.x;
            acc[d4*4+1] += sm*vv.y;
            acc[d4*4+2] += sm*vv.z;
            acc[d4*4+3] += sm*vv.w;
        }
    }

    float* op = outbuf + ((size_t)win*NWTOK + tid) * CC + head*HDIM;
    #pragma unroll
    for (int d = 0; d < HDIM; ++d) op[d] = acc[d] * inv;
}

// ---------------- launch ----------------------------------------------------
extern "C" void kernel_launch(void* const* d_in, const int* in_sizes, int n_in,
                              void* d_out, int out_size)
{
    const float* x        = (const float*)d_in[0];
    const float* norm1_g  = (const float*)d_in[1];
    const float* norm1_b  = (const float*)d_in[2];
    const float* qkv_w    = (const float*)d_in[3];
    const float* qkv_b    = (const float*)d_in[4];
    const float* bias_tab = (const float*)d_in[5];
    const float* proj_w   = (const float*)d_in[6];
    const float* proj_b   = (const float*)d_in[7];
    const float* norm2_g  = (const float*)d_in[8];
    const float* norm2_b  = (const float*)d_in[9];
    const float* fc1_w    = (const float*)d_in[10];
    const float* fc1_b    = (const float*)d_in[11];
    const float* fc2_w    = (const float*)d_in[12];
    const float* fc2_b    = (const float*)d_in[13];
    float* out = (float*)d_out;

    float *xw, *qkvb, *attno, *x2, *h1;
    cudaGetSymbolAddress((void**)&xw,    g_xw);
    cudaGetSymbolAddress((void**)&qkvb,  g_qkv);
    cudaGetSymbolAddress((void**)&attno, g_attnout);
    cudaGetSymbolAddress((void**)&x2,    g_x2);
    cudaGetSymbolAddress((void**)&h1,    g_h1);

    cudaFuncSetAttribute(attn_kernel, cudaFuncAttributeMaxDynamicSharedMemorySize, ATTN_SMEM);

    // 1. LN1 + window partition
    ln_kernel<<<TOKENS/8, 256>>>(x, norm1_g, norm1_b, xw, 1);

    // 2. QKV GEMM  [262144 x 192] @ [192 x 576]
    gemm_kernel<<<dim3(TOKENS/BM, QKVDIM/BN), 256>>>(xw, qkv_w, qkv_b, qkvb,
                                                     TOKENS, QKVDIM, CC, 0, nullptr);

    // 3. windowed attention
    attn_kernel<<<dim3(HEADS, NWIN), 128, ATTN_SMEM>>>(qkvb, bias_tab, attno);

    // 4. proj GEMM + window-reverse + shortcut residual
    gemm_kernel<<<dim3(TOKENS/BM, CC/BN), 256>>>(attno, proj_w, proj_b, x2,
                                                 TOKENS, CC, CC, 3, x);

    // 5. LN2
    ln_kernel<<<TOKENS/8, 256>>>(x2, norm2_g, norm2_b, xw, 0);

    // 6. FC1 + GELU
    gemm_kernel<<<dim3(TOKENS/BM, HIDDEN/BN), 256>>>(xw, fc1_w, fc1_b, h1,
                                                     TOKENS, HIDDEN, CC, 1, nullptr);

    // 7. FC2 + residual -> output
    gemm_kernel<<<dim3(TOKENS/BM, CC/BN), 256>>>(h1, fc2_w, fc2_b, out,
                                                 TOKENS, CC, HIDDEN, 2, x2);
}

// round 3
// speedup vs baseline: 1.4323x; 1.4323x over previous
#include <cuda_runtime.h>
#include <math.h>
#include <stdint.h>

// ---------------- problem constants ----------------
#define BATCH 2
#define TT 8
#define HH 128
#define WWD 128
#define CC 192
#define TOKENS (BATCH*TT*HH*WWD)         // 262144
#define NWIN 2048
#define NWTOK 128
#define HEADS 6
#define HDIM 32
#define HIDDEN 768
#define QKVDIM 576
#define ATTSCALE 0.17677669529663687f

// ---------------- scratch ----------------
__device__ float g_xw[(size_t)TOKENS * CC];
__device__ float g_qkv[(size_t)NWIN * NWTOK * QKVDIM];
__device__ float g_attnout[(size_t)TOKENS * CC];
__device__ float g_x2[(size_t)TOKENS * CC];
__device__ float g_h1[(size_t)TOKENS * HIDDEN];
__device__ float g_wq[QKVDIM * CC];
__device__ float g_wp[CC * CC];
__device__ float g_w1[HIDDEN * CC];
__device__ float g_w2[CC * HIDDEN];

// ---------------- helpers ----------------
__device__ __forceinline__ float to_tf32(float x) {
    float r;
    asm("cvt.rna.tf32.f32 %0, %1;" : "=f"(r) : "f"(x));
    return r;
}
__device__ __forceinline__ void cp_async16(uint32_t dst, const void* src) {
    asm volatile("cp.async.cg.shared.global [%0], [%1], 16;" :: "r"(dst), "l"(src));
}
__device__ __forceinline__ void cp_commit() { asm volatile("cp.async.commit_group;"); }
__device__ __forceinline__ void cp_wait1()  { asm volatile("cp.async.wait_group 1;"); }
__device__ __forceinline__ uint32_t smem_u32(const void* p) {
    uint32_t a;
    asm("{ .reg .u64 t; cvta.to.shared.u64 t, %1; cvt.u32.u64 %0, t; }" : "=r"(a) : "l"(p));
    return a;
}
__device__ __forceinline__ void mma_tf32(float c[4], const uint32_t a[4], const uint32_t b[2]) {
    asm volatile(
        "mma.sync.aligned.m16n8k8.row.col.f32.tf32.tf32.f32 "
        "{%0,%1,%2,%3}, {%4,%5,%6,%7}, {%8,%9}, {%0,%1,%2,%3};"
        : "+f"(c[0]), "+f"(c[1]), "+f"(c[2]), "+f"(c[3])
        : "r"(a[0]), "r"(a[1]), "r"(a[2]), "r"(a[3]), "r"(b[0]), "r"(b[1]));
}
__device__ __forceinline__ float gelu_exact(float x) {
    return 0.5f * x * (1.0f + erff(x * 0.70710678118654752f));
}

// ---------------- LayerNorm (+tf32 round, optional window scatter) ----------
__global__ void ln_kernel(const float* __restrict__ in,
                          const float* __restrict__ g,
                          const float* __restrict__ b,
                          float* __restrict__ out, int windowed)
{
    int token = (blockIdx.x << 3) + (threadIdx.x >> 5);
    int lane  = threadIdx.x & 31;
    size_t base = (size_t)token * CC;

    float v[6]; float s = 0.f;
    #pragma unroll
    for (int j = 0; j < 6; ++j) { v[j] = in[base + lane + 32*j]; s += v[j]; }
    #pragma unroll
    for (int o = 16; o; o >>= 1) s += __shfl_xor_sync(0xffffffffu, s, o);
    float mu = s * (1.0f/192.0f);
    float vs = 0.f;
    #pragma unroll
    for (int j = 0; j < 6; ++j) { float d = v[j]-mu; vs += d*d; }
    #pragma unroll
    for (int o = 16; o; o >>= 1) vs += __shfl_xor_sync(0xffffffffu, vs, o);
    float rinv = rsqrtf(vs * (1.0f/192.0f) + 1e-5f);

    size_t obase;
    if (windowed) {
        int w = token & 127, h = (token >> 7) & 127, t = (token >> 14) & 7, bb = token >> 17;
        int win = ((bb*4 + (t >> 1))*16 + (h >> 3))*16 + (w >> 3);
        int n   = ((t & 1) << 6) | ((h & 7) << 3) | (w & 7);
        obase = ((size_t)win * NWTOK + n) * CC;
    } else obase = base;
    #pragma unroll
    for (int j = 0; j < 6; ++j) {
        int c = lane + 32*j;
        out[obase + c] = to_tf32((v[j]-mu)*rinv*g[c] + b[c]);
    }
}

// ---------------- tf32 weight rounding ----------------
__global__ void round_tf32_kernel(const float* __restrict__ in, float* __restrict__ out, int n) {
    int i = blockIdx.x * 256 + threadIdx.x;
    if (i < n) out[i] = to_tf32(in[i]);
}

// ---------------- tf32 mma.sync GEMM: out[M,N]=A[M,K]@W[N,K]^T + bias ------
// modes: 0 plain  1 GELU+tf32round  2 +resid  3 +window-reverse scatter +resid
#define BM 256
#define BN 64
#define BK 16
#define PAD 20                               // floats per smem row (stride)
#define STG_FLOATS (BM*PAD + BN*PAD)         // 6400
#define GSMEM (2*STG_FLOATS*4)               // 51200 bytes

__device__ __forceinline__ void load_tiles(const float* __restrict__ A, const float* __restrict__ W,
                                           int K, int row0, int col0, int kt,
                                           float* sA, float* sB, int tid)
{
    uint32_t aA = smem_u32(sA), aB = smem_u32(sB);
    const float* as = A + (size_t)(row0 + tid)*K + kt;
    #pragma unroll
    for (int c4 = 0; c4 < 4; ++c4)
        cp_async16(aA + (uint32_t)(tid*PAD + c4*4)*4, as + c4*4);
    const float* bs = W + (size_t)(col0 + (tid >> 2))*K + kt + (tid & 3)*4;
    cp_async16(aB + (uint32_t)((tid >> 2)*PAD + (tid & 3)*4)*4, bs);
}

__global__ __launch_bounds__(256, 1)
void gemm_mma(const float* __restrict__ A, const float* __restrict__ W,
              const float* __restrict__ bias, float* __restrict__ out,
              int N, int K, int mode, const float* __restrict__ resid)
{
    extern __shared__ float smem[];
    float* sA[2] = { smem,              smem + STG_FLOATS };
    float* sB[2] = { smem + BM*PAD,     smem + STG_FLOATS + BM*PAD };

    int tid = threadIdx.x;
    int lane = tid & 31, wid = tid >> 5;
    int warp_m = wid & 3, warp_n = wid >> 2;       // 4 x 2 warps, warp tile 64x32
    int row0 = blockIdx.x * BM;
    int col0 = blockIdx.y * BN;
    int NC = K / BK;

    float acc[4][4][4];
    #pragma unroll
    for (int i = 0; i < 4; ++i)
        #pragma unroll
        for (int j = 0; j < 4; ++j)
            #pragma unroll
            for (int k = 0; k < 4; ++k) acc[i][j][k] = 0.f;

    int r0 = lane >> 2, c0 = lane & 3;

    load_tiles(A, W, K, row0, col0, 0, sA[0], sB[0], tid);
    cp_commit();

    for (int i = 0; i < NC; ++i) {
        __syncthreads();   // protect buffer (i+1)&1 from overwrite while still in use
        if (i + 1 < NC)
            load_tiles(A, W, K, row0, col0, (i+1)*BK, sA[(i+1)&1], sB[(i+1)&1], tid);
        cp_commit();
        cp_wait1();
        __syncthreads();

        const float* As = sA[i & 1];
        const float* Bs = sB[i & 1];
        const float* ap = As + (warp_m*64 + r0)*PAD + c0;
        const float* bp = Bs + (warp_n*32 + r0)*PAD + c0;

        #pragma unroll
        for (int kk = 0; kk < 2; ++kk) {
            uint32_t af[4][4], bf[4][2];
            #pragma unroll
            for (int mf = 0; mf < 4; ++mf) {
                af[mf][0] = __float_as_uint(ap[(mf*16    )*PAD + kk*8    ]);
                af[mf][1] = __float_as_uint(ap[(mf*16 + 8)*PAD + kk*8    ]);
                af[mf][2] = __float_as_uint(ap[(mf*16    )*PAD + kk*8 + 4]);
                af[mf][3] = __float_as_uint(ap[(mf*16 + 8)*PAD + kk*8 + 4]);
            }
            #pragma unroll
            for (int nf = 0; nf < 4; ++nf) {
                bf[nf][0] = __float_as_uint(bp[nf*8*PAD + kk*8    ]);
                bf[nf][1] = __float_as_uint(bp[nf*8*PAD + kk*8 + 4]);
            }
            #pragma unroll
            for (int mf = 0; mf < 4; ++mf)
                #pragma unroll
                for (int nf = 0; nf < 4; ++nf)
                    mma_tf32(acc[mf][nf], af[mf], bf[nf]);
        }
    }

    // ---------------- epilogue ----------------
    #pragma unroll
    for (int mf = 0; mf < 4; ++mf) {
        #pragma unroll
        for (int half = 0; half < 2; ++half) {
            int gm = row0 + warp_m*64 + mf*16 + half*8 + r0;
            size_t rowbase;
            if (mode == 3) {
                int win = gm >> 7, n = gm & 127;
                int bb = win >> 10, rem = win & 1023;
                int t = (rem >> 8)*2 + (n >> 6);
                int h = ((rem >> 4) & 15)*8 + ((n >> 3) & 7);
                int w = (rem & 15)*8 + (n & 7);
                rowbase = (size_t)(((bb*TT + t)*HH + h)*WWD + w) * CC;
            } else {
                rowbase = (size_t)gm * N;
            }
            #pragma unroll
            for (int nf = 0; nf < 4; ++nf) {
                int gn = col0 + warp_n*32 + nf*8 + c0*2;
                float v0 = acc[mf][nf][half*2 + 0] + bias[gn];
                float v1 = acc[mf][nf][half*2 + 1] + bias[gn + 1];
                if (mode == 1) {
                    v0 = to_tf32(gelu_exact(v0));
                    v1 = to_tf32(gelu_exact(v1));
                } else if (mode >= 2) {
                    const float2 rr = *(const float2*)(resid + rowbase + gn);
                    v0 += rr.x; v1 += rr.y;
                }
                float2 o; o.x = v0; o.y = v1;
                *(float2*)(out + rowbase + gn) = o;
            }
        }
    }
}

// ---------------- attention (SIMT, tf32-rounded output) --------------------
#define KP 36
#define SP 129
#define ATTN_SMEM ((2*128*KP + 128*SP) * 4)

__global__ __launch_bounds__(128)
void attn_kernel(const float* __restrict__ qkv,
                 const float* __restrict__ bias_table,
                 float* __restrict__ outbuf)
{
    extern __shared__ float fsm[];
    float* ks = fsm;
    float* vs = fsm + 128*KP;
    float* S  = fsm + 2*128*KP;

    int head = blockIdx.x, win = blockIdx.y, tid = threadIdx.x;
    size_t base = (size_t)win * (NWTOK * QKVDIM);
    int qo = head*HDIM, ko = CC + head*HDIM, vo = 2*CC + head*HDIM;

    for (int idx = tid; idx < NWTOK*HDIM; idx += 128) {
        int r = idx >> 5, c = idx & 31;
        ks[r*KP + c] = qkv[base + (size_t)r*QKVDIM + ko + c];
        vs[r*KP + c] = qkv[base + (size_t)r*QKVDIM + vo + c];
    }
    float qr[HDIM];
    {
        const float* qp = qkv + base + (size_t)tid*QKVDIM + qo;
        #pragma unroll
        for (int d = 0; d < HDIM; ++d) qr[d] = qp[d] * ATTSCALE;
    }
    __syncthreads();

    int t1 = tid >> 6, h1 = (tid >> 3) & 7, w1 = tid & 7;
    float mx = -1e30f;
    for (int m = 0; m < NWTOK; ++m) {
        const float4* kp = (const float4*)(ks + m*KP);
        float dot = 0.f;
        #pragma unroll
        for (int d4 = 0; d4 < 8; ++d4) {
            float4 kv = kp[d4];
            dot += qr[d4*4+0]*kv.x + qr[d4*4+1]*kv.y + qr[d4*4+2]*kv.z + qr[d4*4+3]*kv.w;
        }
        int t2 = m >> 6, h2 = (m >> 3) & 7, w2 = m & 7;
        int bi = (t1-t2+1)*225 + (h1-h2+7)*15 + (w1-w2+7);
        dot += __ldg(bias_table + bi*HEADS + head);
        S[tid*SP + m] = dot;
        mx = fmaxf(mx, dot);
    }
    float sum = 0.f;
    for (int m = 0; m < NWTOK; ++m) {
        float e = __expf(S[tid*SP + m] - mx);
        S[tid*SP + m] = e;
        sum += e;
    }
    float inv = 1.0f / sum;

    float acc[HDIM] = {};
    for (int m = 0; m < NWTOK; ++m) {
        float sm = S[tid*SP + m];
        const float4* vp = (const float4*)(vs + m*KP);
        #pragma unroll
        for (int d4 = 0; d4 < 8; ++d4) {
            float4 vv = vp[d4];
            acc[d4*4+0] += sm*vv.x; acc[d4*4+1] += sm*vv.y;
            acc[d4*4+2] += sm*vv.z; acc[d4*4+3] += sm*vv.w;
        }
    }
    float* op = outbuf + ((size_t)win*NWTOK + tid)*CC + head*HDIM;
    #pragma unroll
    for (int d = 0; d < HDIM; ++d) op[d] = to_tf32(acc[d] * inv);
}

// ---------------- launch ----------------
extern "C" void kernel_launch(void* const* d_in, const int* in_sizes, int n_in,
                              void* d_out, int out_size)
{
    const float* x        = (const float*)d_in[0];
    const float* norm1_g  = (const float*)d_in[1];
    const float* norm1_b  = (const float*)d_in[2];
    const float* qkv_w    = (const float*)d_in[3];
    const float* qkv_b    = (const float*)d_in[4];
    const float* bias_tab = (const float*)d_in[5];
    const float* proj_w   = (const float*)d_in[6];
    const float* proj_b   = (const float*)d_in[7];
    const float* norm2_g  = (const float*)d_in[8];
    const float* norm2_b  = (const float*)d_in[9];
    const float* fc1_w    = (const float*)d_in[10];
    const float* fc1_b    = (const float*)d_in[11];
    const float* fc2_w    = (const float*)d_in[12];
    const float* fc2_b    = (const float*)d_in[13];
    float* out = (float*)d_out;

    float *xw, *qkvb, *attno, *x2, *h1, *wq, *wp, *w1, *w2;
    cudaGetSymbolAddress((void**)&xw,    g_xw);
    cudaGetSymbolAddress((void**)&qkvb,  g_qkv);
    cudaGetSymbolAddress((void**)&attno, g_attnout);
    cudaGetSymbolAddress((void**)&x2,    g_x2);
    cudaGetSymbolAddress((void**)&h1,    g_h1);
    cudaGetSymbolAddress((void**)&wq,    g_wq);
    cudaGetSymbolAddress((void**)&wp,    g_wp);
    cudaGetSymbolAddress((void**)&w1,    g_w1);
    cudaGetSymbolAddress((void**)&w2,    g_w2);

    cudaFuncSetAttribute(attn_kernel, cudaFuncAttributeMaxDynamicSharedMemorySize, ATTN_SMEM);
    cudaFuncSetAttribute(gemm_mma,    cudaFuncAttributeMaxDynamicSharedMemorySize, GSMEM);

    // weight rounding (tf32 RNA)
    round_tf32_kernel<<<(QKVDIM*CC+255)/256, 256>>>(qkv_w, wq, QKVDIM*CC);
    round_tf32_kernel<<<(CC*CC+255)/256,     256>>>(proj_w, wp, CC*CC);
    round_tf32_kernel<<<(HIDDEN*CC+255)/256, 256>>>(fc1_w, w1, HIDDEN*CC);
    round_tf32_kernel<<<(CC*HIDDEN+255)/256, 256>>>(fc2_w, w2, CC*HIDDEN);

    // 1. LN1 + window partition (tf32)
    ln_kernel<<<TOKENS/8, 256>>>(x, norm1_g, norm1_b, xw, 1);
    // 2. QKV GEMM
    gemm_mma<<<dim3(TOKENS/BM, QKVDIM/BN), 256, GSMEM>>>(xw, wq, qkv_b, qkvb, QKVDIM, CC, 0, nullptr);
    // 3. windowed attention
    attn_kernel<<<dim3(HEADS, NWIN), 128, ATTN_SMEM>>>(qkvb, bias_tab, attno);
    // 4. proj + window-reverse + residual
    gemm_mma<<<dim3(TOKENS/BM, CC/BN), 256, GSMEM>>>(attno, wp, proj_b, x2, CC, CC, 3, x);
    // 5. LN2
    ln_kernel<<<TOKENS/8, 256>>>(x2, norm2_g, norm2_b, xw, 0);
    // 6. FC1 + GELU (tf32)
    gemm_mma<<<dim3(TOKENS/BM, HIDDEN/BN), 256, GSMEM>>>(xw, w1, fc1_b, h1, HIDDEN, CC, 1, nullptr);
    // 7. FC2 + residual -> out
    gemm_mma<<<dim3(TOKENS/BM, CC/BN), 256, GSMEM>>>(h1, w2, fc2_b, out, CC, HIDDEN, 2, x2);
}

// round 4
// speedup vs baseline: 1.7863x; 1.2472x over previous
#include <cuda_runtime.h>
#include <math.h>
#include <stdint.h>

// ---------------- problem constants ----------------
#define BATCH 2
#define TT 8
#define HH 128
#define WWD 128
#define CC 192
#define TOKENS (BATCH*TT*HH*WWD)         // 262144
#define NWIN 2048
#define NWTOK 128
#define HEADS 6
#define HDIM 32
#define HIDDEN 768
#define QKVDIM 576
#define ATTSCALE 0.17677669529663687f

// ---------------- scratch ----------------
__device__ float g_xw[(size_t)TOKENS * CC];
__device__ float g_qkv[(size_t)NWIN * NWTOK * QKVDIM];
__device__ float g_attnout[(size_t)TOKENS * CC];
__device__ float g_x2[(size_t)TOKENS * CC];
__device__ float g_h1[(size_t)TOKENS * HIDDEN];
__device__ float g_wq[QKVDIM * CC];
__device__ float g_wp[CC * CC];
__device__ float g_w1[HIDDEN * CC];
__device__ float g_w2[CC * HIDDEN];

// ---------------- helpers ----------------
__device__ __forceinline__ float to_tf32(float x) {
    float r;
    asm("cvt.rna.tf32.f32 %0, %1;" : "=f"(r) : "f"(x));
    return r;
}
__device__ __forceinline__ void cp_async16(uint32_t dst, const void* src) {
    asm volatile("cp.async.cg.shared.global [%0], [%1], 16;" :: "r"(dst), "l"(src));
}
__device__ __forceinline__ void cp_commit() { asm volatile("cp.async.commit_group;"); }
__device__ __forceinline__ void cp_wait1()  { asm volatile("cp.async.wait_group 1;"); }
__device__ __forceinline__ uint32_t smem_u32(const void* p) {
    uint32_t a;
    asm("{ .reg .u64 t; cvta.to.shared.u64 t, %1; cvt.u32.u64 %0, t; }" : "=r"(a) : "l"(p));
    return a;
}
__device__ __forceinline__ void mma_tf32(float c[4], const uint32_t a[4], const uint32_t b[2]) {
    asm volatile(
        "mma.sync.aligned.m16n8k8.row.col.f32.tf32.tf32.f32 "
        "{%0,%1,%2,%3}, {%4,%5,%6,%7}, {%8,%9}, {%0,%1,%2,%3};"
        : "+f"(c[0]), "+f"(c[1]), "+f"(c[2]), "+f"(c[3])
        : "r"(a[0]), "r"(a[1]), "r"(a[2]), "r"(a[3]), "r"(b[0]), "r"(b[1]));
}
__device__ __forceinline__ float gelu_exact(float x) {
    return 0.5f * x * (1.0f + erff(x * 0.70710678118654752f));
}

// ---------------- LayerNorm (+tf32 round, optional window scatter) ----------
__global__ void ln_kernel(const float* __restrict__ in,
                          const float* __restrict__ g,
                          const float* __restrict__ b,
                          float* __restrict__ out, int windowed)
{
    int token = (blockIdx.x << 3) + (threadIdx.x >> 5);
    int lane  = threadIdx.x & 31;
    size_t base = (size_t)token * CC;

    float v[6]; float s = 0.f;
    #pragma unroll
    for (int j = 0; j < 6; ++j) { v[j] = in[base + lane + 32*j]; s += v[j]; }
    #pragma unroll
    for (int o = 16; o; o >>= 1) s += __shfl_xor_sync(0xffffffffu, s, o);
    float mu = s * (1.0f/192.0f);
    float vs = 0.f;
    #pragma unroll
    for (int j = 0; j < 6; ++j) { float d = v[j]-mu; vs += d*d; }
    #pragma unroll
    for (int o = 16; o; o >>= 1) vs += __shfl_xor_sync(0xffffffffu, vs, o);
    float rinv = rsqrtf(vs * (1.0f/192.0f) + 1e-5f);

    size_t obase;
    if (windowed) {
        int w = token & 127, h = (token >> 7) & 127, t = (token >> 14) & 7, bb = token >> 17;
        int win = ((bb*4 + (t >> 1))*16 + (h >> 3))*16 + (w >> 3);
        int n   = ((t & 1) << 6) | ((h & 7) << 3) | (w & 7);
        obase = ((size_t)win * NWTOK + n) * CC;
    } else obase = base;
    #pragma unroll
    for (int j = 0; j < 6; ++j) {
        int c = lane + 32*j;
        out[obase + c] = to_tf32((v[j]-mu)*rinv*g[c] + b[c]);
    }
}

// ---------------- tf32 weight rounding ----------------
__global__ void round_tf32_kernel(const float* __restrict__ in, float* __restrict__ out, int n) {
    int i = blockIdx.x * 256 + threadIdx.x;
    if (i < n) out[i] = to_tf32(in[i]);
}

// ---------------- tf32 mma.sync GEMM: out[M,N]=A[M,K]@W[N,K]^T + bias ------
// modes: 0 plain  1 GELU+tf32round  2 +resid  3 +window-reverse scatter +resid
#define BM 128
#define BN 192
#define BK 16
#define PAD 20                               // floats per smem row (stride)
#define STG_FLOATS (BM*PAD + BN*PAD)         // 6400
#define GSMEM (2*STG_FLOATS*4)               // 51200 bytes

__device__ __forceinline__ void load_tiles(const float* __restrict__ A, const float* __restrict__ W,
                                           int K, int row0, int col0, int kt,
                                           float* sA, float* sB, int tid)
{
    uint32_t aA = smem_u32(sA), aB = smem_u32(sB);
    #pragma unroll
    for (int j = 0; j < 2; ++j) {            // A: 128 rows x 4 float4
        int idx = tid + j*256;
        int r = idx >> 2, c4 = idx & 3;
        cp_async16(aA + (uint32_t)(r*PAD + c4*4)*4, A + (size_t)(row0 + r)*K + kt + c4*4);
    }
    #pragma unroll
    for (int j = 0; j < 3; ++j) {            // B: 192 rows x 4 float4
        int idx = tid + j*256;
        int r = idx >> 2, c4 = idx & 3;
        cp_async16(aB + (uint32_t)(r*PAD + c4*4)*4, W + (size_t)(col0 + r)*K + kt + c4*4);
    }
}

__global__ __launch_bounds__(256, 1)
void gemm_mma(const float* __restrict__ A, const float* __restrict__ W,
              const float* __restrict__ bias, float* __restrict__ out,
              int N, int K, int mode, const float* __restrict__ resid)
{
    extern __shared__ float smem[];
    float* sA[2] = { smem,              smem + STG_FLOATS };
    float* sB[2] = { smem + BM*PAD,     smem + STG_FLOATS + BM*PAD };

    int tid = threadIdx.x;
    int lane = tid & 31, wid = tid >> 5;
    int warp_m = wid & 1, warp_n = wid >> 1;       // 2 x 4 warps, warp tile 64x48
    int row0 = blockIdx.x * BM;
    int col0 = blockIdx.y * BN;
    int NC = K / BK;

    float acc[4][6][4];
    #pragma unroll
    for (int i = 0; i < 4; ++i)
        #pragma unroll
        for (int j = 0; j < 6; ++j)
            #pragma unroll
            for (int k = 0; k < 4; ++k) acc[i][j][k] = 0.f;

    int r0 = lane >> 2, c0 = lane & 3;

    load_tiles(A, W, K, row0, col0, 0, sA[0], sB[0], tid);
    cp_commit();

    for (int i = 0; i < NC; ++i) {
        __syncthreads();   // protect buffer (i+1)&1 from overwrite while still in use
        if (i + 1 < NC)
            load_tiles(A, W, K, row0, col0, (i+1)*BK, sA[(i+1)&1], sB[(i+1)&1], tid);
        cp_commit();
        cp_wait1();
        __syncthreads();

        const float* As = sA[i & 1];
        const float* Bs = sB[i & 1];
        const float* ap = As + (warp_m*64 + r0)*PAD + c0;
        const float* bp = Bs + (warp_n*48 + r0)*PAD + c0;

        #pragma unroll
        for (int kk = 0; kk < 2; ++kk) {
            uint32_t af[4][4], bf[6][2];
            #pragma unroll
            for (int mf = 0; mf < 4; ++mf) {
                af[mf][0] = __float_as_uint(ap[(mf*16    )*PAD + kk*8    ]);
                af[mf][1] = __float_as_uint(ap[(mf*16 + 8)*PAD + kk*8    ]);
                af[mf][2] = __float_as_uint(ap[(mf*16    )*PAD + kk*8 + 4]);
                af[mf][3] = __float_as_uint(ap[(mf*16 + 8)*PAD + kk*8 + 4]);
            }
            #pragma unroll
            for (int nf = 0; nf < 6; ++nf) {
                bf[nf][0] = __float_as_uint(bp[nf*8*PAD + kk*8    ]);
                bf[nf][1] = __float_as_uint(bp[nf*8*PAD + kk*8 + 4]);
            }
            #pragma unroll
            for (int mf = 0; mf < 4; ++mf)
                #pragma unroll
                for (int nf = 0; nf < 6; ++nf)
                    mma_tf32(acc[mf][nf], af[mf], bf[nf]);
        }
    }

    // ---------------- epilogue ----------------
    #pragma unroll
    for (int mf = 0; mf < 4; ++mf) {
        #pragma unroll
        for (int half = 0; half < 2; ++half) {
            int gm = row0 + warp_m*64 + mf*16 + half*8 + r0;
            size_t rowbase;
            if (mode == 3) {
                int win = gm >> 7, n = gm & 127;
                int bb = win >> 10, rem = win & 1023;
                int t = (rem >> 8)*2 + (n >> 6);
                int h = ((rem >> 4) & 15)*8 + ((n >> 3) & 7);
                int w = (rem & 15)*8 + (n & 7);
                rowbase = (size_t)(((bb*TT + t)*HH + h)*WWD + w) * CC;
            } else {
                rowbase = (size_t)gm * N;
            }
            #pragma unroll
            for (int nf = 0; nf < 6; ++nf) {
                int gn = col0 + warp_n*48 + nf*8 + c0*2;
                float v0 = acc[mf][nf][half*2 + 0] + bias[gn];
                float v1 = acc[mf][nf][half*2 + 1] + bias[gn + 1];
                if (mode == 1) {
                    v0 = to_tf32(gelu_exact(v0));
                    v1 = to_tf32(gelu_exact(v1));
                } else if (mode >= 2) {
                    const float2 rr = *(const float2*)(resid + rowbase + gn);
                    v0 += rr.x; v1 += rr.y;
                }
                float2 o; o.x = v0; o.y = v1;
                *(float2*)(out + rowbase + gn) = o;
            }
        }
    }
}

// ---------------- attention (SIMT, tf32-rounded output) --------------------
#define KP 36
#define SP 129
#define ATTN_SMEM ((2*128*KP + 128*SP) * 4)

__global__ __launch_bounds__(128)
void attn_kernel(const float* __restrict__ qkv,
                 const float* __restrict__ bias_table,
                 float* __restrict__ outbuf)
{
    extern __shared__ float fsm[];
    float* ks = fsm;
    float* vs = fsm + 128*KP;
    float* S  = fsm + 2*128*KP;

    int head = blockIdx.x, win = blockIdx.y, tid = threadIdx.x;
    size_t base = (size_t)win * (NWTOK * QKVDIM);
    int qo = head*HDIM, ko = CC + head*HDIM, vo = 2*CC + head*HDIM;

    for (int idx = tid; idx < NWTOK*HDIM; idx += 128) {
        int r = idx >> 5, c = idx & 31;
        ks[r*KP + c] = qkv[base + (size_t)r*QKVDIM + ko + c];
        vs[r*KP + c] = qkv[base + (size_t)r*QKVDIM + vo + c];
    }
    float qr[HDIM];
    {
        const float* qp = qkv + base + (size_t)tid*QKVDIM + qo;
        #pragma unroll
        for (int d = 0; d < HDIM; ++d) qr[d] = qp[d] * ATTSCALE;
    }
    __syncthreads();

    int t1 = tid >> 6, h1 = (tid >> 3) & 7, w1 = tid & 7;
    float mx = -1e30f;
    for (int m = 0; m < NWTOK; ++m) {
        const float4* kp = (const float4*)(ks + m*KP);
        float dot = 0.f;
        #pragma unroll
        for (int d4 = 0; d4 < 8; ++d4) {
            float4 kv = kp[d4];
            dot += qr[d4*4+0]*kv.x + qr[d4*4+1]*kv.y + qr[d4*4+2]*kv.z + qr[d4*4+3]*kv.w;
        }
        int t2 = m >> 6, h2 = (m >> 3) & 7, w2 = m & 7;
        int bi = (t1-t2+1)*225 + (h1-h2+7)*15 + (w1-w2+7);
        dot += __ldg(bias_table + bi*HEADS + head);
        S[tid*SP + m] = dot;
        mx = fmaxf(mx, dot);
    }
    float sum = 0.f;
    for (int m = 0; m < NWTOK; ++m) {
        float e = __expf(S[tid*SP + m] - mx);
        S[tid*SP + m] = e;
        sum += e;
    }
    float inv = 1.0f / sum;

    float acc[HDIM] = {};
    for (int m = 0; m < NWTOK; ++m) {
        float sm = S[tid*SP + m];
        const float4* vp = (const float4*)(vs + m*KP);
        #pragma unroll
        for (int d4 = 0; d4 < 8; ++d4) {
            float4 vv = vp[d4];
            acc[d4*4+0] += sm*vv.x; acc[d4*4+1] += sm*vv.y;
            acc[d4*4+2] += sm*vv.z; acc[d4*4+3] += sm*vv.w;
        }
    }
    float* op = outbuf + ((size_t)win*NWTOK + tid)*CC + head*HDIM;
    #pragma unroll
    for (int d = 0; d < HDIM; ++d) op[d] = to_tf32(acc[d] * inv);
}

// ---------------- launch ----------------
extern "C" void kernel_launch(void* const* d_in, const int* in_sizes, int n_in,
                              void* d_out, int out_size)
{
    const float* x        = (const float*)d_in[0];
    const float* norm1_g  = (const float*)d_in[1];
    const float* norm1_b  = (const float*)d_in[2];
    const float* qkv_w    = (const float*)d_in[3];
    const float* qkv_b    = (const float*)d_in[4];
    const float* bias_tab = (const float*)d_in[5];
    const float* proj_w   = (const float*)d_in[6];
    const float* proj_b   = (const float*)d_in[7];
    const float* norm2_g  = (const float*)d_in[8];
    const float* norm2_b  = (const float*)d_in[9];
    const float* fc1_w    = (const float*)d_in[10];
    const float* fc1_b    = (const float*)d_in[11];
    const float* fc2_w    = (const float*)d_in[12];
    const float* fc2_b    = (const float*)d_in[13];
    float* out = (float*)d_out;

    float *xw, *qkvb, *attno, *x2, *h1, *wq, *wp, *w1, *w2;
    cudaGetSymbolAddress((void**)&xw,    g_xw);
    cudaGetSymbolAddress((void**)&qkvb,  g_qkv);
    cudaGetSymbolAddress((void**)&attno, g_attnout);
    cudaGetSymbolAddress((void**)&x2,    g_x2);
    cudaGetSymbolAddress((void**)&h1,    g_h1);
    cudaGetSymbolAddress((void**)&wq,    g_wq);
    cudaGetSymbolAddress((void**)&wp,    g_wp);
    cudaGetSymbolAddress((void**)&w1,    g_w1);
    cudaGetSymbolAddress((void**)&w2,    g_w2);

    cudaFuncSetAttribute(attn_kernel, cudaFuncAttributeMaxDynamicSharedMemorySize, ATTN_SMEM);
    cudaFuncSetAttribute(gemm_mma,    cudaFuncAttributeMaxDynamicSharedMemorySize, GSMEM);

    // weight rounding (tf32 RNA)
    round_tf32_kernel<<<(QKVDIM*CC+255)/256, 256>>>(qkv_w, wq, QKVDIM*CC);
    round_tf32_kernel<<<(CC*CC+255)/256,     256>>>(proj_w, wp, CC*CC);
    round_tf32_kernel<<<(HIDDEN*CC+255)/256, 256>>>(fc1_w, w1, HIDDEN*CC);
    round_tf32_kernel<<<(CC*HIDDEN+255)/256, 256>>>(fc2_w, w2, CC*HIDDEN);

    // 1. LN1 + window partition (tf32)
    ln_kernel<<<TOKENS/8, 256>>>(x, norm1_g, norm1_b, xw, 1);
    // 2. QKV GEMM
    gemm_mma<<<dim3(TOKENS/BM, QKVDIM/BN), 256, GSMEM>>>(xw, wq, qkv_b, qkvb, QKVDIM, CC, 0, nullptr);
    // 3. windowed attention
    attn_kernel<<<dim3(HEADS, NWIN), 128, ATTN_SMEM>>>(qkvb, bias_tab, attno);
    // 4. proj + window-reverse + residual
    gemm_mma<<<dim3(TOKENS/BM, CC/BN), 256, GSMEM>>>(attno, wp, proj_b, x2, CC, CC, 3, x);
    // 5. LN2
    ln_kernel<<<TOKENS/8, 256>>>(x2, norm2_g, norm2_b, xw, 0);
    // 6. FC1 + GELU (tf32)
    gemm_mma<<<dim3(TOKENS/BM, HIDDEN/BN), 256, GSMEM>>>(xw, w1, fc1_b, h1, HIDDEN, CC, 1, nullptr);
    // 7. FC2 + residual -> out
    gemm_mma<<<dim3(TOKENS/BM, CC/BN), 256, GSMEM>>>(h1, w2, fc2_b, out, CC, HIDDEN, 2, x2);
}

// round 5
// speedup vs baseline: 2.5801x; 1.4443x over previous
#include <cuda_runtime.h>
#include <math.h>
#include <stdint.h>

// ---------------- problem constants ----------------
#define BATCH 2
#define TT 8
#define HH 128
#define WWD 128
#define CC 192
#define TOKENS (BATCH*TT*HH*WWD)         // 262144
#define NWIN 2048
#define NWTOK 128
#define HEADS 6
#define HDIM 32
#define HIDDEN 768
#define QKVDIM 576
#define ATTSCALE 0.17677669529663687f

// ---------------- scratch ----------------
__device__ float g_xw[(size_t)TOKENS * CC];
__device__ float g_qkv[(size_t)NWIN * NWTOK * QKVDIM];
__device__ float g_attnout[(size_t)TOKENS * CC];
__device__ float g_x2[(size_t)TOKENS * CC];
__device__ float g_h1[(size_t)TOKENS * HIDDEN];
__device__ float g_wq[QKVDIM * CC];
__device__ float g_wp[CC * CC];
__device__ float g_w1[HIDDEN * CC];
__device__ float g_w2[CC * HIDDEN];
__device__ float g_biasf[HEADS * NWTOK * NWTOK];   // expanded rel-pos bias

// ---------------- helpers ----------------
__device__ __forceinline__ float to_tf32(float x) {
    float r;
    asm("cvt.rna.tf32.f32 %0, %1;" : "=f"(r) : "f"(x));
    return r;
}
__device__ __forceinline__ void cp_async16(uint32_t dst, const void* src) {
    asm volatile("cp.async.cg.shared.global [%0], [%1], 16;" :: "r"(dst), "l"(src));
}
__device__ __forceinline__ void cp_commit() { asm volatile("cp.async.commit_group;"); }
__device__ __forceinline__ void cp_wait1()  { asm volatile("cp.async.wait_group 1;"); }
__device__ __forceinline__ uint32_t smem_u32(const void* p) {
    uint32_t a;
    asm("{ .reg .u64 t; cvta.to.shared.u64 t, %1; cvt.u32.u64 %0, t; }" : "=r"(a) : "l"(p));
    return a;
}
__device__ __forceinline__ void mma_tf32(float c[4], const uint32_t a[4], const uint32_t b[2]) {
    asm volatile(
        "mma.sync.aligned.m16n8k8.row.col.f32.tf32.tf32.f32 "
        "{%0,%1,%2,%3}, {%4,%5,%6,%7}, {%8,%9}, {%0,%1,%2,%3};"
        : "+f"(c[0]), "+f"(c[1]), "+f"(c[2]), "+f"(c[3])
        : "r"(a[0]), "r"(a[1]), "r"(a[2]), "r"(a[3]), "r"(b[0]), "r"(b[1]));
}
__device__ __forceinline__ float gelu_exact(float x) {
    return 0.5f * x * (1.0f + erff(x * 0.70710678118654752f));
}

// ---------------- LayerNorm (+tf32 round, optional window scatter) ----------
__global__ void ln_kernel(const float* __restrict__ in,
                          const float* __restrict__ g,
                          const float* __restrict__ b,
                          float* __restrict__ out, int windowed)
{
    int token = (blockIdx.x << 3) + (threadIdx.x >> 5);
    int lane  = threadIdx.x & 31;
    size_t base = (size_t)token * CC;

    float v[6]; float s = 0.f;
    #pragma unroll
    for (int j = 0; j < 6; ++j) { v[j] = in[base + lane + 32*j]; s += v[j]; }
    #pragma unroll
    for (int o = 16; o; o >>= 1) s += __shfl_xor_sync(0xffffffffu, s, o);
    float mu = s * (1.0f/192.0f);
    float vs = 0.f;
    #pragma unroll
    for (int j = 0; j < 6; ++j) { float d = v[j]-mu; vs += d*d; }
    #pragma unroll
    for (int o = 16; o; o >>= 1) vs += __shfl_xor_sync(0xffffffffu, vs, o);
    float rinv = rsqrtf(vs * (1.0f/192.0f) + 1e-5f);

    size_t obase;
    if (windowed) {
        int w = token & 127, h = (token >> 7) & 127, t = (token >> 14) & 7, bb = token >> 17;
        int win = ((bb*4 + (t >> 1))*16 + (h >> 3))*16 + (w >> 3);
        int n   = ((t & 1) << 6) | ((h & 7) << 3) | (w & 7);
        obase = ((size_t)win * NWTOK + n) * CC;
    } else obase = base;
    #pragma unroll
    for (int j = 0; j < 6; ++j) {
        int c = lane + 32*j;
        out[obase + c] = to_tf32((v[j]-mu)*rinv*g[c] + b[c]);
    }
}

// ---------------- tf32 weight rounding ----------------
__global__ void round_tf32_kernel(const float* __restrict__ in, float* __restrict__ out, int n) {
    int i = blockIdx.x * 256 + threadIdx.x;
    if (i < n) out[i] = to_tf32(in[i]);
}

// ---------------- expand relative-position bias: [head][n][m] -------------
__global__ void bias_expand_kernel(const float* __restrict__ bt, float* __restrict__ bf) {
    int idx = blockIdx.x * 256 + threadIdx.x;
    if (idx >= HEADS*NWTOK*NWTOK) return;
    int h = idx >> 14, rem = idx & 16383, n = rem >> 7, m = rem & 127;
    int t1 = n >> 6, h1 = (n >> 3) & 7, w1 = n & 7;
    int t2 = m >> 6, h2 = (m >> 3) & 7, w2 = m & 7;
    int bi = (t1 - t2 + 1)*225 + (h1 - h2 + 7)*15 + (w1 - w2 + 7);
    bf[idx] = bt[bi*HEADS + h];
}

// ---------------- tf32 mma.sync GEMM: out[M,N]=A[M,K]@W[N,K]^T + bias ------
// modes: 0 plain  1 GELU+tf32round  2 +resid  3 +window-reverse scatter +resid
#define BM 128
#define BN 192
#define BK 16
#define PAD 20
#define STG_FLOATS (BM*PAD + BN*PAD)
#define GSMEM (2*STG_FLOATS*4)

__device__ __forceinline__ void load_tiles(const float* __restrict__ A, const float* __restrict__ W,
                                           int K, int row0, int col0, int kt,
                                           float* sA, float* sB, int tid)
{
    uint32_t aA = smem_u32(sA), aB = smem_u32(sB);
    #pragma unroll
    for (int j = 0; j < 2; ++j) {
        int idx = tid + j*256;
        int r = idx >> 2, c4 = idx & 3;
        cp_async16(aA + (uint32_t)(r*PAD + c4*4)*4, A + (size_t)(row0 + r)*K + kt + c4*4);
    }
    #pragma unroll
    for (int j = 0; j < 3; ++j) {
        int idx = tid + j*256;
        int r = idx >> 2, c4 = idx & 3;
        cp_async16(aB + (uint32_t)(r*PAD + c4*4)*4, W + (size_t)(col0 + r)*K + kt + c4*4);
    }
}

__global__ __launch_bounds__(256, 1)
void gemm_mma(const float* __restrict__ A, const float* __restrict__ W,
              const float* __restrict__ bias, float* __restrict__ out,
              int N, int K, int mode, const float* __restrict__ resid)
{
    extern __shared__ float smem[];
    float* sA[2] = { smem,              smem + STG_FLOATS };
    float* sB[2] = { smem + BM*PAD,     smem + STG_FLOATS + BM*PAD };

    int tid = threadIdx.x;
    int lane = tid & 31, wid = tid >> 5;
    int warp_m = wid & 1, warp_n = wid >> 1;
    int row0 = blockIdx.x * BM;
    int col0 = blockIdx.y * BN;
    int NC = K / BK;

    float acc[4][6][4];
    #pragma unroll
    for (int i = 0; i < 4; ++i)
        #pragma unroll
        for (int j = 0; j < 6; ++j)
            #pragma unroll
            for (int k = 0; k < 4; ++k) acc[i][j][k] = 0.f;

    int r0 = lane >> 2, c0 = lane & 3;

    load_tiles(A, W, K, row0, col0, 0, sA[0], sB[0], tid);
    cp_commit();

    for (int i = 0; i < NC; ++i) {
        __syncthreads();
        if (i + 1 < NC)
            load_tiles(A, W, K, row0, col0, (i+1)*BK, sA[(i+1)&1], sB[(i+1)&1], tid);
        cp_commit();
        cp_wait1();
        __syncthreads();

        const float* As = sA[i & 1];
        const float* Bs = sB[i & 1];
        const float* ap = As + (warp_m*64 + r0)*PAD + c0;
        const float* bp = Bs + (warp_n*48 + r0)*PAD + c0;

        #pragma unroll
        for (int kk = 0; kk < 2; ++kk) {
            uint32_t af[4][4], bf[6][2];
            #pragma unroll
            for (int mf = 0; mf < 4; ++mf) {
                af[mf][0] = __float_as_uint(ap[(mf*16    )*PAD + kk*8    ]);
                af[mf][1] = __float_as_uint(ap[(mf*16 + 8)*PAD + kk*8    ]);
                af[mf][2] = __float_as_uint(ap[(mf*16    )*PAD + kk*8 + 4]);
                af[mf][3] = __float_as_uint(ap[(mf*16 + 8)*PAD + kk*8 + 4]);
            }
            #pragma unroll
            for (int nf = 0; nf < 6; ++nf) {
                bf[nf][0] = __float_as_uint(bp[nf*8*PAD + kk*8    ]);
                bf[nf][1] = __float_as_uint(bp[nf*8*PAD + kk*8 + 4]);
            }
            #pragma unroll
            for (int mf = 0; mf < 4; ++mf)
                #pragma unroll
                for (int nf = 0; nf < 6; ++nf)
                    mma_tf32(acc[mf][nf], af[mf], bf[nf]);
        }
    }

    #pragma unroll
    for (int mf = 0; mf < 4; ++mf) {
        #pragma unroll
        for (int half = 0; half < 2; ++half) {
            int gm = row0 + warp_m*64 + mf*16 + half*8 + r0;
            size_t rowbase;
            if (mode == 3) {
                int win = gm >> 7, n = gm & 127;
                int bb = win >> 10, rem = win & 1023;
                int t = (rem >> 8)*2 + (n >> 6);
                int h = ((rem >> 4) & 15)*8 + ((n >> 3) & 7);
                int w = (rem & 15)*8 + (n & 7);
                rowbase = (size_t)(((bb*TT + t)*HH + h)*WWD + w) * CC;
            } else {
                rowbase = (size_t)gm * N;
            }
            #pragma unroll
            for (int nf = 0; nf < 6; ++nf) {
                int gn = col0 + warp_n*48 + nf*8 + c0*2;
                float v0 = acc[mf][nf][half*2 + 0] + bias[gn];
                float v1 = acc[mf][nf][half*2 + 1] + bias[gn + 1];
                if (mode == 1) {
                    v0 = to_tf32(gelu_exact(v0));
                    v1 = to_tf32(gelu_exact(v1));
                } else if (mode >= 2) {
                    const float2 rr = *(const float2*)(resid + rowbase + gn);
                    v0 += rr.x; v1 += rr.y;
                }
                float2 o; o.x = v0; o.y = v1;
                *(float2*)(out + rowbase + gn) = o;
            }
        }
    }
}

// ---------------- attention via tf32 mma ------------------------------------
// one block per (head, window); 4 warps. smem: P[128][132] (overlays Q,K) + Vt[32][132]
#define QP 36
#define PP 132
#define ATT_SMEM ((128*PP + 32*PP)*4)     // 84480 bytes

__global__ __launch_bounds__(128)
void attn_mma(const float* __restrict__ qkv,
              const float* __restrict__ biasf,
              float* __restrict__ outp)
{
    extern __shared__ float sm[];
    float* Ps  = sm;                 // 128*132
    float* Qs  = sm;                 // overlays Ps[0:4608]
    float* Ks  = sm + 128*QP;        // overlays Ps[4608:9216]
    float* Vts = sm + 128*PP;        // 32*132

    int head = blockIdx.x, win = blockIdx.y;
    int tid = threadIdx.x, lane = tid & 31, w = tid >> 5;
    int r0 = lane >> 2, c0 = lane & 3;

    // ---- stage Q (scaled), K, V^T with tf32 rounding ----
    {
        const float* rb = qkv + (size_t)win*NWTOK*QKVDIM + (size_t)tid*QKVDIM + head*HDIM;
        const float4* qp = (const float4*)(rb);
        const float4* kp = (const float4*)(rb + CC);
        const float4* vp = (const float4*)(rb + 2*CC);
        #pragma unroll
        for (int j = 0; j < 8; ++j) {
            float4 q = qp[j];
            Qs[tid*QP + 4*j+0] = to_tf32(q.x*ATTSCALE);
            Qs[tid*QP + 4*j+1] = to_tf32(q.y*ATTSCALE);
            Qs[tid*QP + 4*j+2] = to_tf32(q.z*ATTSCALE);
            Qs[tid*QP + 4*j+3] = to_tf32(q.w*ATTSCALE);
            float4 k = kp[j];
            Ks[tid*QP + 4*j+0] = to_tf32(k.x);
            Ks[tid*QP + 4*j+1] = to_tf32(k.y);
            Ks[tid*QP + 4*j+2] = to_tf32(k.z);
            Ks[tid*QP + 4*j+3] = to_tf32(k.w);
            float4 v = vp[j];
            Vts[(4*j+0)*PP + tid] = to_tf32(v.x);
            Vts[(4*j+1)*PP + tid] = to_tf32(v.y);
            Vts[(4*j+2)*PP + tid] = to_tf32(v.z);
            Vts[(4*j+3)*PP + tid] = to_tf32(v.w);
        }
    }
    __syncthreads();

    // ---- S = Q K^T : warp w rows [32w, 32w+32) ----
    float s[2][16][4];
    #pragma unroll
    for (int a = 0; a < 2; ++a)
        #pragma unroll
        for (int b = 0; b < 16; ++b)
            #pragma unroll
            for (int c = 0; c < 4; ++c) s[a][b][c] = 0.f;

    {
        const float* aq = Qs + (w*32 + r0)*QP + c0;
        const float* bk = Ks + r0*QP + c0;
        #pragma unroll
        for (int kk = 0; kk < 4; ++kk) {
            uint32_t af[2][4];
            #pragma unroll
            for (int mf = 0; mf < 2; ++mf) {
                af[mf][0] = __float_as_uint(aq[(mf*16    )*QP + kk*8    ]);
                af[mf][1] = __float_as_uint(aq[(mf*16 + 8)*QP + kk*8    ]);
                af[mf][2] = __float_as_uint(aq[(mf*16    )*QP + kk*8 + 4]);
                af[mf][3] = __float_as_uint(aq[(mf*16 + 8)*QP + kk*8 + 4]);
            }
            #pragma unroll
            for (int nf = 0; nf < 16; ++nf) {
                uint32_t bf[2];
                bf[0] = __float_as_uint(bk[nf*8*QP + kk*8    ]);
                bf[1] = __float_as_uint(bk[nf*8*QP + kk*8 + 4]);
                mma_tf32(s[0][nf], af[0], bf);
                mma_tf32(s[1][nf], af[1], bf);
            }
        }
    }

    // ---- bias add + row softmax (normalization deferred) ----
    float inv[2][2];
    const float* bh = biasf + (size_t)head*NWTOK*NWTOK;
    #pragma unroll
    for (int mf = 0; mf < 2; ++mf) {
        #pragma unroll
        for (int half = 0; half < 2; ++half) {
            int r = w*32 + mf*16 + half*8 + r0;
            const float2* brow = (const float2*)(bh + r*NWTOK) + c0;
            float mx = -1e30f;
            #pragma unroll
            for (int nf = 0; nf < 16; ++nf) {
                float2 bb = brow[nf*4];
                float v0 = s[mf][nf][half*2+0] + bb.x;
                float v1 = s[mf][nf][half*2+1] + bb.y;
                s[mf][nf][half*2+0] = v0;
                s[mf][nf][half*2+1] = v1;
                mx = fmaxf(mx, fmaxf(v0, v1));
            }
            mx = fmaxf(mx, __shfl_xor_sync(0xffffffffu, mx, 1));
            mx = fmaxf(mx, __shfl_xor_sync(0xffffffffu, mx, 2));
            float sum = 0.f;
            #pragma unroll
            for (int nf = 0; nf < 16; ++nf) {
                float e0 = __expf(s[mf][nf][half*2+0] - mx);
                float e1 = __expf(s[mf][nf][half*2+1] - mx);
                s[mf][nf][half*2+0] = e0;
                s[mf][nf][half*2+1] = e1;
                sum += e0 + e1;
            }
            sum += __shfl_xor_sync(0xffffffffu, sum, 1);
            sum += __shfl_xor_sync(0xffffffffu, sum, 2);
            inv[mf][half] = 1.0f / sum;
        }
    }

    __syncthreads();   // all warps done reading Qs/Ks before P overwrites

    // ---- store P (tf32) to smem ----
    #pragma unroll
    for (int mf = 0; mf < 2; ++mf) {
        #pragma unroll
        for (int half = 0; half < 2; ++half) {
            int r = w*32 + mf*16 + half*8 + r0;
            float* pr = Ps + r*PP + 2*c0;
            #pragma unroll
            for (int nf = 0; nf < 16; ++nf) {
                float2 o;
                o.x = to_tf32(s[mf][nf][half*2+0]);
                o.y = to_tf32(s[mf][nf][half*2+1]);
                *(float2*)(pr + nf*8) = o;
            }
        }
    }
    __syncthreads();

    // ---- O = P V : warp rows x 32 dims ----
    float o[2][4][4];
    #pragma unroll
    for (int a = 0; a < 2; ++a)
        #pragma unroll
        for (int b = 0; b < 4; ++b)
            #pragma unroll
            for (int c = 0; c < 4; ++c) o[a][b][c] = 0.f;

    {
        const float* ap = Ps + (w*32 + r0)*PP + c0;
        const float* bv = Vts + r0*PP + c0;
        #pragma unroll
        for (int kk = 0; kk < 16; ++kk) {
            uint32_t af[2][4];
            #pragma unroll
            for (int mf = 0; mf < 2; ++mf) {
                af[mf][0] = __float_as_uint(ap[(mf*16    )*PP + kk*8    ]);
                af[mf][1] = __float_as_uint(ap[(mf*16 + 8)*PP + kk*8    ]);
                af[mf][2] = __float_as_uint(ap[(mf*16    )*PP + kk*8 + 4]);
                af[mf][3] = __float_as_uint(ap[(mf*16 + 8)*PP + kk*8 + 4]);
            }
            #pragma unroll
            for (int nf = 0; nf < 4; ++nf) {
                uint32_t bf[2];
                bf[0] = __float_as_uint(bv[nf*8*PP + kk*8    ]);
                bf[1] = __float_as_uint(bv[nf*8*PP + kk*8 + 4]);
                mma_tf32(o[0][nf], af[0], bf);
                mma_tf32(o[1][nf], af[1], bf);
            }
        }
    }

    // ---- epilogue: normalize + tf32 round + store ----
    #pragma unroll
    for (int mf = 0; mf < 2; ++mf) {
        #pragma unroll
        for (int half = 0; half < 2; ++half) {
            int r = w*32 + mf*16 + half*8 + r0;
            float sc = inv[mf][half];
            float* op = outp + ((size_t)win*NWTOK + r)*CC + head*HDIM;
            #pragma unroll
            for (int nf = 0; nf < 4; ++nf) {
                int d = nf*8 + 2*c0;
                float2 ov;
                ov.x = to_tf32(o[mf][nf][half*2+0] * sc);
                ov.y = to_tf32(o[mf][nf][half*2+1] * sc);
                *(float2*)(op + d) = ov;
            }
        }
    }
}

// ---------------- launch ----------------
extern "C" void kernel_launch(void* const* d_in, const int* in_sizes, int n_in,
                              void* d_out, int out_size)
{
    const float* x        = (const float*)d_in[0];
    const float* norm1_g  = (const float*)d_in[1];
    const float* norm1_b  = (const float*)d_in[2];
    const float* qkv_w    = (const float*)d_in[3];
    const float* qkv_b    = (const float*)d_in[4];
    const float* bias_tab = (const float*)d_in[5];
    const float* proj_w   = (const float*)d_in[6];
    const float* proj_b   = (const float*)d_in[7];
    const float* norm2_g  = (const float*)d_in[8];
    const float* norm2_b  = (const float*)d_in[9];
    const float* fc1_w    = (const float*)d_in[10];
    const float* fc1_b    = (const float*)d_in[11];
    const float* fc2_w    = (const float*)d_in[12];
    const float* fc2_b    = (const float*)d_in[13];
    float* out = (float*)d_out;

    float *xw, *qkvb, *attno, *x2, *h1, *wq, *wp, *w1, *w2, *bf;
    cudaGetSymbolAddress((void**)&xw,    g_xw);
    cudaGetSymbolAddress((void**)&qkvb,  g_qkv);
    cudaGetSymbolAddress((void**)&attno, g_attnout);
    cudaGetSymbolAddress((void**)&x2,    g_x2);
    cudaGetSymbolAddress((void**)&h1,    g_h1);
    cudaGetSymbolAddress((void**)&wq,    g_wq);
    cudaGetSymbolAddress((void**)&wp,    g_wp);
    cudaGetSymbolAddress((void**)&w1,    g_w1);
    cudaGetSymbolAddress((void**)&w2,    g_w2);
    cudaGetSymbolAddress((void**)&bf,    g_biasf);

    cudaFuncSetAttribute(attn_mma, cudaFuncAttributeMaxDynamicSharedMemorySize, ATT_SMEM);
    cudaFuncSetAttribute(gemm_mma, cudaFuncAttributeMaxDynamicSharedMemorySize, GSMEM);

    // weight rounding + bias expansion
    round_tf32_kernel<<<(QKVDIM*CC+255)/256, 256>>>(qkv_w, wq, QKVDIM*CC);
    round_tf32_kernel<<<(CC*CC+255)/256,     256>>>(proj_w, wp, CC*CC);
    round_tf32_kernel<<<(HIDDEN*CC+255)/256, 256>>>(fc1_w, w1, HIDDEN*CC);
    round_tf32_kernel<<<(CC*HIDDEN+255)/256, 256>>>(fc2_w, w2, CC*HIDDEN);
    bias_expand_kernel<<<(HEADS*NWTOK*NWTOK+255)/256, 256>>>(bias_tab, bf);

    // 1. LN1 + window partition (tf32)
    ln_kernel<<<TOKENS/8, 256>>>(x, norm1_g, norm1_b, xw, 1);
    // 2. QKV GEMM
    gemm_mma<<<dim3(TOKENS/BM, QKVDIM/BN), 256, GSMEM>>>(xw, wq, qkv_b, qkvb, QKVDIM, CC, 0, nullptr);
    // 3. windowed attention (tensor-core)
    attn_mma<<<dim3(HEADS, NWIN), 128, ATT_SMEM>>>(qkvb, bf, attno);
    // 4. proj + window-reverse + residual
    gemm_mma<<<dim3(TOKENS/BM, CC/BN), 256, GSMEM>>>(attno, wp, proj_b, x2, CC, CC, 3, x);
    // 5. LN2
    ln_kernel<<<TOKENS/8, 256>>>(x2, norm2_g, norm2_b, xw, 0);
    // 6. FC1 + GELU (tf32)
    gemm_mma<<<dim3(TOKENS/BM, HIDDEN/BN), 256, GSMEM>>>(xw, w1, fc1_b, h1, HIDDEN, CC, 1, nullptr);
    // 7. FC2 + residual -> out
    gemm_mma<<<dim3(TOKENS/BM, CC/BN), 256, GSMEM>>>(h1, w2, fc2_b, out, CC, HIDDEN, 2, x2);
}

// round 7
// speedup vs baseline: 4.1677x; 1.6154x over previous
#include <cuda_runtime.h>
#include <cuda_fp16.h>
#include <math.h>
#include <stdint.h>

// ---------------- problem constants ----------------
#define BATCH 2
#define TT 8
#define HH 128
#define WWD 128
#define CC 192
#define TOKENS (BATCH*TT*HH*WWD)         // 262144
#define NWIN 2048
#define NWTOK 128
#define HEADS 6
#define HDIM 32
#define HIDDEN 768
#define QKVDIM 576
#define ATTSCALE 0.17677669529663687f

// ---------------- scratch ----------------
__device__ __half g_xw[(size_t)TOKENS * CC];
__device__ __half g_qkv[(size_t)NWIN * NWTOK * QKVDIM];
__device__ __half g_attnout[(size_t)TOKENS * CC];
__device__ float  g_x2[(size_t)TOKENS * CC];
__device__ __half g_h1[(size_t)TOKENS * HIDDEN];
__device__ __half g_wq[QKVDIM * CC];
__device__ __half g_wp[CC * CC];
__device__ __half g_w1[HIDDEN * CC];
__device__ __half g_w2[CC * HIDDEN];
__device__ float  g_biasf[HEADS * NWTOK * NWTOK];

// ---------------- helpers ----------------
__device__ __forceinline__ void cp_async16(uint32_t dst, const void* src) {
    asm volatile("cp.async.cg.shared.global [%0], [%1], 16;" :: "r"(dst), "l"(src));
}
__device__ __forceinline__ void cp_commit() { asm volatile("cp.async.commit_group;"); }
__device__ __forceinline__ void cp_wait1()  { asm volatile("cp.async.wait_group 1;"); }
__device__ __forceinline__ uint32_t smem_u32(const void* p) {
    uint32_t a;
    asm("{ .reg .u64 t; cvta.to.shared.u64 t, %1; cvt.u32.u64 %0, t; }" : "=r"(a) : "l"(p));
    return a;
}
__device__ __forceinline__ void mma_f16(float c[4], const uint32_t a[4], const uint32_t b[2]) {
    asm volatile(
        "mma.sync.aligned.m16n8k16.row.col.f32.f16.f16.f32 "
        "{%0,%1,%2,%3}, {%4,%5,%6,%7}, {%8,%9}, {%0,%1,%2,%3};"
        : "+f"(c[0]), "+f"(c[1]), "+f"(c[2]), "+f"(c[3])
        : "r"(a[0]), "r"(a[1]), "r"(a[2]), "r"(a[3]), "r"(b[0]), "r"(b[1]));
}
__device__ __forceinline__ float gelu_exact(float x) {
    return 0.5f * x * (1.0f + erff(x * 0.70710678118654752f));
}
__device__ __forceinline__ uint32_t ldh2(const __half* p) { return *(const uint32_t*)p; }

// ---------------- LayerNorm -> half (optional window scatter) ---------------
__global__ void ln_kernel(const float* __restrict__ in,
                          const float* __restrict__ g,
                          const float* __restrict__ b,
                          __half* __restrict__ out, int windowed)
{
    int token = (blockIdx.x << 3) + (threadIdx.x >> 5);
    int lane  = threadIdx.x & 31;
    size_t base = (size_t)token * CC;

    float v[6]; float s = 0.f;
    #pragma unroll
    for (int j = 0; j < 6; ++j) { v[j] = in[base + lane + 32*j]; s += v[j]; }
    #pragma unroll
    for (int o = 16; o; o >>= 1) s += __shfl_xor_sync(0xffffffffu, s, o);
    float mu = s * (1.0f/192.0f);
    float vs = 0.f;
    #pragma unroll
    for (int j = 0; j < 6; ++j) { float d = v[j]-mu; vs += d*d; }
    #pragma unroll
    for (int o = 16; o; o >>= 1) vs += __shfl_xor_sync(0xffffffffu, vs, o);
    float rinv = rsqrtf(vs * (1.0f/192.0f) + 1e-5f);

    size_t obase;
    if (windowed) {
        int w = token & 127, h = (token >> 7) & 127, t = (token >> 14) & 7, bb = token >> 17;
        int win = ((bb*4 + (t >> 1))*16 + (h >> 3))*16 + (w >> 3);
        int n   = ((t & 1) << 6) | ((h & 7) << 3) | (w & 7);
        obase = ((size_t)win * NWTOK + n) * CC;
    } else obase = base;
    #pragma unroll
    for (int j = 0; j < 6; ++j) {
        int c = lane + 32*j;
        out[obase + c] = __float2half_rn((v[j]-mu)*rinv*g[c] + b[c]);
    }
}

// ---------------- fp32 -> fp16 weight conversion ----------------
__global__ void cvt_half_kernel(const float* __restrict__ in, __half* __restrict__ out, int n) {
    int i = blockIdx.x * 256 + threadIdx.x;
    if (i < n) out[i] = __float2half_rn(in[i]);
}

// ---------------- expand relative-position bias: [head][n][m] -------------
__global__ void bias_expand_kernel(const float* __restrict__ bt, float* __restrict__ bf) {
    int idx = blockIdx.x * 256 + threadIdx.x;
    if (idx >= HEADS*NWTOK*NWTOK) return;
    int h = idx >> 14, rem = idx & 16383, n = rem >> 7, m = rem & 127;
    int t1 = n >> 6, h1 = (n >> 3) & 7, w1 = n & 7;
    int t2 = m >> 6, h2 = (m >> 3) & 7, w2 = m & 7;
    int bi = (t1 - t2 + 1)*225 + (h1 - h2 + 7)*15 + (w1 - w2 + 7);
    bf[idx] = bt[bi*HEADS + h];
}

// ---------------- fp16 mma GEMM: out[M,N]=A[M,K]@W[N,K]^T + bias -----------
// modes: 0 plain->half  1 GELU->half  2 +resid->f32  3 +win-reverse +resid->f32
#define BM 128
#define BN 192
#define BK 32                               // halves per K chunk
#define PADH 40                             // halves per smem row (80B)
#define STG_BYTES ((BM + BN) * PADH * 2)    // 25600
#define GSMEM (2*STG_BYTES)                 // 51200

__device__ __forceinline__ void load_tiles(const __half* __restrict__ A, const __half* __restrict__ W,
                                           int K, int row0, int col0, int kt,
                                           __half* sA, __half* sB, int tid)
{
    uint32_t aA = smem_u32(sA), aB = smem_u32(sB);
    #pragma unroll
    for (int j = 0; j < 2; ++j) {            // A: 128 rows x 4 x 16B
        int idx = tid + j*256;
        int r = idx >> 2, c4 = idx & 3;
        cp_async16(aA + (uint32_t)(r*PADH + c4*8)*2, A + (size_t)(row0 + r)*K + kt + c4*8);
    }
    #pragma unroll
    for (int j = 0; j < 3; ++j) {            // B: 192 rows x 4 x 16B
        int idx = tid + j*256;
        int r = idx >> 2, c4 = idx & 3;
        cp_async16(aB + (uint32_t)(r*PADH + c4*8)*2, W + (size_t)(col0 + r)*K + kt + c4*8);
    }
}

__global__ __launch_bounds__(256, 1)
void gemm_mma(const __half* __restrict__ A, const __half* __restrict__ W,
              const float* __restrict__ bias, void* __restrict__ outv,
              int N, int K, int mode, const float* __restrict__ resid)
{
    extern __shared__ __half smh[];
    __half* sA[2] = { smh,            smh + STG_BYTES/2 };
    __half* sB[2] = { smh + BM*PADH,  smh + STG_BYTES/2 + BM*PADH };

    int tid = threadIdx.x;
    int lane = tid & 31, wid = tid >> 5;
    int warp_m = wid & 1, warp_n = wid >> 1;       // 2 x 4 warps, warp tile 64x48
    int col0 = blockIdx.x * BN;                    // col = x for L2 A-reuse
    int row0 = blockIdx.y * BM;
    int NC = K / BK;

    float acc[4][6][4];
    #pragma unroll
    for (int i = 0; i < 4; ++i)
        #pragma unroll
        for (int j = 0; j < 6; ++j)
            #pragma unroll
            for (int k = 0; k < 4; ++k) acc[i][j][k] = 0.f;

    int r0 = lane >> 2, c0 = lane & 3;

    load_tiles(A, W, K, row0, col0, 0, sA[0], sB[0], tid);
    cp_commit();

    for (int i = 0; i < NC; ++i) {
        __syncthreads();
        if (i + 1 < NC)
            load_tiles(A, W, K, row0, col0, (i+1)*BK, sA[(i+1)&1], sB[(i+1)&1], tid);
        cp_commit();
        cp_wait1();
        __syncthreads();

        const __half* ap = sA[i & 1] + (warp_m*64 + r0)*PADH + 2*c0;
        const __half* bp = sB[i & 1] + (warp_n*48 + r0)*PADH + 2*c0;

        #pragma unroll
        for (int kk = 0; kk < 2; ++kk) {
            int k0 = kk*16;
            uint32_t af[4][4], bf[6][2];
            #pragma unroll
            for (int mf = 0; mf < 4; ++mf) {
                af[mf][0] = ldh2(ap + (mf*16    )*PADH + k0    );
                af[mf][1] = ldh2(ap + (mf*16 + 8)*PADH + k0    );
                af[mf][2] = ldh2(ap + (mf*16    )*PADH + k0 + 8);
                af[mf][3] = ldh2(ap + (mf*16 + 8)*PADH + k0 + 8);
            }
            #pragma unroll
            for (int nf = 0; nf < 6; ++nf) {
                bf[nf][0] = ldh2(bp + nf*8*PADH + k0    );
                bf[nf][1] = ldh2(bp + nf*8*PADH + k0 + 8);
            }
            #pragma unroll
            for (int mf = 0; mf < 4; ++mf)
                #pragma unroll
                for (int nf = 0; nf < 6; ++nf)
                    mma_f16(acc[mf][nf], af[mf], bf[nf]);
        }
    }

    // ---------------- epilogue ----------------
    #pragma unroll
    for (int mf = 0; mf < 4; ++mf) {
        #pragma unroll
        for (int half = 0; half < 2; ++half) {
            int gm = row0 + warp_m*64 + mf*16 + half*8 + r0;
            size_t rowbase;
            if (mode == 3) {
                int win = gm >> 7, n = gm & 127;
                int bb = win >> 10, rem = win & 1023;
                int t = (rem >> 8)*2 + (n >> 6);
                int h = ((rem >> 4) & 15)*8 + ((n >> 3) & 7);
                int w = (rem & 15)*8 + (n & 7);
                rowbase = (size_t)(((bb*TT + t)*HH + h)*WWD + w) * CC;
            } else {
                rowbase = (size_t)gm * N;
            }
            #pragma unroll
            for (int nf = 0; nf < 6; ++nf) {
                int gn = col0 + warp_n*48 + nf*8 + c0*2;
                float v0 = acc[mf][nf][half*2 + 0] + bias[gn];
                float v1 = acc[mf][nf][half*2 + 1] + bias[gn + 1];
                if (mode == 0) {
                    *(__half2*)((__half*)outv + rowbase + gn) = __floats2half2_rn(v0, v1);
                } else if (mode == 1) {
                    *(__half2*)((__half*)outv + rowbase + gn) =
                        __floats2half2_rn(gelu_exact(v0), gelu_exact(v1));
                } else {
                    const float2 rr = *(const float2*)(resid + rowbase + gn);
                    float2 o; o.x = v0 + rr.x; o.y = v1 + rr.y;
                    *(float2*)((float*)outv + rowbase + gn) = o;
                }
            }
        }
    }
}

// ---------------- attention via fp16 mma ------------------------------------
// one block per (head, window); 4 warps.
// halves: Ps 128x136 (overlays Qs 128x40 + Ks 128x40), Vts 32x136
#define PQH 40
#define PPH 136
#define ATT_SMEM ((128*PPH + 32*PPH)*2)     // 43520 bytes

__global__ __launch_bounds__(128)
void attn_mma(const __half* __restrict__ qkv,
              const float* __restrict__ biasf,
              __half* __restrict__ outp)
{
    extern __shared__ __half sh[];
    __half* Ps  = sh;                    // 128*136
    __half* Qs  = sh;                    // overlay
    __half* Ks  = sh + 128*PQH;          // overlay (ends at 10240 halves < 128*136)
    __half* Vts = sh + 128*PPH;          // 32*136

    int head = blockIdx.x, win = blockIdx.y;
    int tid = threadIdx.x, lane = tid & 31, w = tid >> 5;
    int r0 = lane >> 2, c0 = lane & 3;

    // ---- stage Q, K (full 32 halves each) and V^T ----
    {
        const __half* rb = qkv + (size_t)win*NWTOK*QKVDIM + (size_t)tid*QKVDIM + head*HDIM;
        const uint4* q4 = (const uint4*)(rb);
        const uint4* k4 = (const uint4*)(rb + CC);
        const uint4* v4 = (const uint4*)(rb + 2*CC);
        uint4* qd = (uint4*)(Qs + tid*PQH);
        uint4* kd = (uint4*)(Ks + tid*PQH);
        qd[0] = q4[0]; qd[1] = q4[1]; qd[2] = q4[2]; qd[3] = q4[3];
        kd[0] = k4[0]; kd[1] = k4[1]; kd[2] = k4[2]; kd[3] = k4[3];
        uint4 va = v4[0], vb = v4[1], vc = v4[2], vd2 = v4[3];
        const __half* vh = (const __half*)&va;
        #pragma unroll
        for (int d = 0; d < 8; ++d) Vts[d*PPH + tid] = vh[d];
        vh = (const __half*)&vb;
        #pragma unroll
        for (int d = 0; d < 8; ++d) Vts[(d+8)*PPH + tid] = vh[d];
        vh = (const __half*)&vc;
        #pragma unroll
        for (int d = 0; d < 8; ++d) Vts[(d+16)*PPH + tid] = vh[d];
        vh = (const __half*)&vd2;
        #pragma unroll
        for (int d = 0; d < 8; ++d) Vts[(d+24)*PPH + tid] = vh[d];
    }
    __syncthreads();

    // ---- S = Q K^T (unscaled; scale folded into bias step) ----
    float s[2][16][4];
    #pragma unroll
    for (int a = 0; a < 2; ++a)
        #pragma unroll
        for (int b = 0; b < 16; ++b)
            #pragma unroll
            for (int c = 0; c < 4; ++c) s[a][b][c] = 0.f;

    {
        const __half* aq = Qs + (w*32 + r0)*PQH + 2*c0;
        const __half* bk = Ks + r0*PQH + 2*c0;
        #pragma unroll
        for (int kk = 0; kk < 2; ++kk) {
            int k0 = kk*16;
            uint32_t af[2][4];
            #pragma unroll
            for (int mf = 0; mf < 2; ++mf) {
                af[mf][0] = ldh2(aq + (mf*16    )*PQH + k0    );
                af[mf][1] = ldh2(aq + (mf*16 + 8)*PQH + k0    );
                af[mf][2] = ldh2(aq + (mf*16    )*PQH + k0 + 8);
                af[mf][3] = ldh2(aq + (mf*16 + 8)*PQH + k0 + 8);
            }
            #pragma unroll
            for (int nf = 0; nf < 16; ++nf) {
                uint32_t bf[2];
                bf[0] = ldh2(bk + nf*8*PQH + k0    );
                bf[1] = ldh2(bk + nf*8*PQH + k0 + 8);
                mma_f16(s[0][nf], af[0], bf);
                mma_f16(s[1][nf], af[1], bf);
            }
        }
    }

    // ---- scale + bias + row softmax (normalization deferred) ----
    float inv[2][2];
    const float* bh = biasf + (size_t)head*NWTOK*NWTOK;
    #pragma unroll
    for (int mf = 0; mf < 2; ++mf) {
        #pragma unroll
        for (int half = 0; half < 2; ++half) {
            int r = w*32 + mf*16 + half*8 + r0;
            const float2* brow = (const float2*)(bh + r*NWTOK) + c0;
            float mx = -1e30f;
            #pragma unroll
            for (int nf = 0; nf < 16; ++nf) {
                float2 bb = brow[nf*4];
                float v0 = s[mf][nf][half*2+0]*ATTSCALE + bb.x;
                float v1 = s[mf][nf][half*2+1]*ATTSCALE + bb.y;
                s[mf][nf][half*2+0] = v0;
                s[mf][nf][half*2+1] = v1;
                mx = fmaxf(mx, fmaxf(v0, v1));
            }
            mx = fmaxf(mx, __shfl_xor_sync(0xffffffffu, mx, 1));
            mx = fmaxf(mx, __shfl_xor_sync(0xffffffffu, mx, 2));
            float sum = 0.f;
            #pragma unroll
            for (int nf = 0; nf < 16; ++nf) {
                float e0 = __expf(s[mf][nf][half*2+0] - mx);
                float e1 = __expf(s[mf][nf][half*2+1] - mx);
                s[mf][nf][half*2+0] = e0;
                s[mf][nf][half*2+1] = e1;
                sum += e0 + e1;
            }
            sum += __shfl_xor_sync(0xffffffffu, sum, 1);
            sum += __shfl_xor_sync(0xffffffffu, sum, 2);
            inv[mf][half] = 1.0f / sum;
        }
    }

    __syncthreads();   // all warps done reading Qs/Ks before P overwrites

    // ---- store P (half) ----
    #pragma unroll
    for (int mf = 0; mf < 2; ++mf) {
        #pragma unroll
        for (int half = 0; half < 2; ++half) {
            int r = w*32 + mf*16 + half*8 + r0;
            __half* pr = Ps + r*PPH + 2*c0;
            #pragma unroll
            for (int nf = 0; nf < 16; ++nf)
                *(__half2*)(pr + nf*8) =
                    __floats2half2_rn(s[mf][nf][half*2+0], s[mf][nf][half*2+1]);
        }
    }
    __syncthreads();

    // ---- O = P V ----
    float o[2][4][4];
    #pragma unroll
    for (int a = 0; a < 2; ++a)
        #pragma unroll
        for (int b = 0; b < 4; ++b)
            #pragma unroll
            for (int c = 0; c < 4; ++c) o[a][b][c] = 0.f;

    {
        const __half* ap = Ps + (w*32 + r0)*PPH + 2*c0;
        const __half* bv = Vts + r0*PPH + 2*c0;
        #pragma unroll
        for (int kk = 0; kk < 8; ++kk) {
            int k0 = kk*16;
            uint32_t af[2][4];
            #pragma unroll
            for (int mf = 0; mf < 2; ++mf) {
                af[mf][0] = ldh2(ap + (mf*16    )*PPH + k0    );
                af[mf][1] = ldh2(ap + (mf*16 + 8)*PPH + k0    );
                af[mf][2] = ldh2(ap + (mf*16    )*PPH + k0 + 8);
                af[mf][3] = ldh2(ap + (mf*16 + 8)*PPH + k0 + 8);
            }
            #pragma unroll
            for (int nf = 0; nf < 4; ++nf) {
                uint32_t bf[2];
                bf[0] = ldh2(bv + nf*8*PPH + k0    );
                bf[1] = ldh2(bv + nf*8*PPH + k0 + 8);
                mma_f16(o[0][nf], af[0], bf);
                mma_f16(o[1][nf], af[1], bf);
            }
        }
    }

    // ---- epilogue: normalize + store half ----
    #pragma unroll
    for (int mf = 0; mf < 2; ++mf) {
        #pragma unroll
        for (int half = 0; half < 2; ++half) {
            int r = w*32 + mf*16 + half*8 + r0;
            float sc = inv[mf][half];
            __half* op = outp + ((size_t)win*NWTOK + r)*CC + head*HDIM;
            #pragma unroll
            for (int nf = 0; nf < 4; ++nf)
                *(__half2*)(op + nf*8 + 2*c0) =
                    __floats2half2_rn(o[mf][nf][half*2+0]*sc, o[mf][nf][half*2+1]*sc);
        }
    }
}

// ---------------- launch ----------------
extern "C" void kernel_launch(void* const* d_in, const int* in_sizes, int n_in,
                              void* d_out, int out_size)
{
    const float* x        = (const float*)d_in[0];
    const float* norm1_g  = (const float*)d_in[1];
    const float* norm1_b  = (const float*)d_in[2];
    const float* qkv_w    = (const float*)d_in[3];
    const float* qkv_b    = (const float*)d_in[4];
    const float* bias_tab = (const float*)d_in[5];
    const float* proj_w   = (const float*)d_in[6];
    const float* proj_b   = (const float*)d_in[7];
    const float* norm2_g  = (const float*)d_in[8];
    const float* norm2_b  = (const float*)d_in[9];
    const float* fc1_w    = (const float*)d_in[10];
    const float* fc1_b    = (const float*)d_in[11];
    const float* fc2_w    = (const float*)d_in[12];
    const float* fc2_b    = (const float*)d_in[13];
    float* out = (float*)d_out;

    __half *xw, *qkvb, *attno, *h1, *wq, *wp, *w1, *w2;
    float *x2, *bf;
    cudaGetSymbolAddress((void**)&xw,    g_xw);
    cudaGetSymbolAddress((void**)&qkvb,  g_qkv);
    cudaGetSymbolAddress((void**)&attno, g_attnout);
    cudaGetSymbolAddress((void**)&x2,    g_x2);
    cudaGetSymbolAddress((void**)&h1,    g_h1);
    cudaGetSymbolAddress((void**)&wq,    g_wq);
    cudaGetSymbolAddress((void**)&wp,    g_wp);
    cudaGetSymbolAddress((void**)&w1,    g_w1);
    cudaGetSymbolAddress((void**)&w2,    g_w2);
    cudaGetSymbolAddress((void**)&bf,    g_biasf);

    cudaFuncSetAttribute(attn_mma, cudaFuncAttributeMaxDynamicSharedMemorySize, ATT_SMEM);
    cudaFuncSetAttribute(gemm_mma, cudaFuncAttributeMaxDynamicSharedMemorySize, GSMEM);

    // weight conversion + bias expansion
    cvt_half_kernel<<<(QKVDIM*CC+255)/256, 256>>>(qkv_w, wq, QKVDIM*CC);
    cvt_half_kernel<<<(CC*CC+255)/256,     256>>>(proj_w, wp, CC*CC);
    cvt_half_kernel<<<(HIDDEN*CC+255)/256, 256>>>(fc1_w, w1, HIDDEN*CC);
    cvt_half_kernel<<<(CC*HIDDEN+255)/256, 256>>>(fc2_w, w2, CC*HIDDEN);
    bias_expand_kernel<<<(HEADS*NWTOK*NWTOK+255)/256, 256>>>(bias_tab, bf);

    // 1. LN1 + window partition -> half
    ln_kernel<<<TOKENS/8, 256>>>(x, norm1_g, norm1_b, xw, 1);
    // 2. QKV GEMM -> half
    gemm_mma<<<dim3(QKVDIM/BN, TOKENS/BM), 256, GSMEM>>>(xw, wq, qkv_b, qkvb, QKVDIM, CC, 0, nullptr);
    // 3. windowed attention -> half
    attn_mma<<<dim3(HEADS, NWIN), 128, ATT_SMEM>>>(qkvb, bf, attno);
    // 4. proj + window-reverse + residual -> f32
    gemm_mma<<<dim3(CC/BN, TOKENS/BM), 256, GSMEM>>>(attno, wp, proj_b, x2, CC, CC, 3, x);
    // 5. LN2 -> half
    ln_kernel<<<TOKENS/8, 256>>>(x2, norm2_g, norm2_b, xw, 0);
    // 6. FC1 + GELU -> half
    gemm_mma<<<dim3(HIDDEN/BN, TOKENS/BM), 256, GSMEM>>>(xw, w1, fc1_b, h1, HIDDEN, CC, 1, nullptr);
    // 7. FC2 + residual -> out (f32)
    gemm_mma<<<dim3(CC/BN, TOKENS/BM), 256, GSMEM>>>(h1, w2, fc2_b, out, CC, HIDDEN, 2, x2);
}

// round 8
// speedup vs baseline: 4.4327x; 1.0636x over previous
#include <cuda_runtime.h>
#include <cuda_fp16.h>
#include <math.h>
#include <stdint.h>

// ---------------- problem constants ----------------
#define BATCH 2
#define TT 8
#define HH 128
#define WWD 128
#define CC 192
#define TOKENS (BATCH*TT*HH*WWD)         // 262144
#define NWIN 2048
#define NWTOK 128
#define HEADS 6
#define HDIM 32
#define HIDDEN 768
#define QKVDIM 576
#define ATTSCALE 0.17677669529663687f

// ---------------- scratch ----------------
__device__ __half g_xw[(size_t)TOKENS * CC];
__device__ __half g_qkv[(size_t)NWIN * NWTOK * QKVDIM];
__device__ __half g_attnout[(size_t)TOKENS * CC];
__device__ float  g_x2[(size_t)TOKENS * CC];
__device__ __half g_h1[(size_t)TOKENS * HIDDEN];
__device__ __half g_wq[QKVDIM * CC];
__device__ __half g_wp[CC * CC];
__device__ __half g_w1[HIDDEN * CC];
__device__ __half g_w2[CC * HIDDEN];
__device__ float  g_biasf[HEADS * NWTOK * NWTOK];

// ---------------- helpers ----------------
__device__ __forceinline__ void cp_async16(uint32_t dst, const void* src) {
    asm volatile("cp.async.cg.shared.global [%0], [%1], 16;" :: "r"(dst), "l"(src));
}
__device__ __forceinline__ void cp_commit() { asm volatile("cp.async.commit_group;"); }
__device__ __forceinline__ void cp_wait1()  { asm volatile("cp.async.wait_group 1;"); }
__device__ __forceinline__ uint32_t smem_u32(const void* p) {
    uint32_t a;
    asm("{ .reg .u64 t; cvta.to.shared.u64 t, %1; cvt.u32.u64 %0, t; }" : "=r"(a) : "l"(p));
    return a;
}
__device__ __forceinline__ void mma_f16(float c[4], const uint32_t a[4], const uint32_t b[2]) {
    asm volatile(
        "mma.sync.aligned.m16n8k16.row.col.f32.f16.f16.f32 "
        "{%0,%1,%2,%3}, {%4,%5,%6,%7}, {%8,%9}, {%0,%1,%2,%3};"
        : "+f"(c[0]), "+f"(c[1]), "+f"(c[2]), "+f"(c[3])
        : "r"(a[0]), "r"(a[1]), "r"(a[2]), "r"(a[3]), "r"(b[0]), "r"(b[1]));
}
__device__ __forceinline__ void ldsm_x4(uint32_t r[4], uint32_t addr) {
    asm volatile("ldmatrix.sync.aligned.m8n8.x4.shared.b16 {%0,%1,%2,%3}, [%4];"
        : "=r"(r[0]), "=r"(r[1]), "=r"(r[2]), "=r"(r[3]) : "r"(addr));
}
__device__ __forceinline__ float gelu_exact(float x) {
    return 0.5f * x * (1.0f + erff(x * 0.70710678118654752f));
}
__device__ __forceinline__ uint32_t ldh2(const __half* p) { return *(const uint32_t*)p; }

// ---------------- LayerNorm -> half (optional window scatter) ---------------
__global__ void ln_kernel(const float* __restrict__ in,
                          const float* __restrict__ g,
                          const float* __restrict__ b,
                          __half* __restrict__ out, int windowed)
{
    int token = (blockIdx.x << 3) + (threadIdx.x >> 5);
    int lane  = threadIdx.x & 31;
    size_t base = (size_t)token * CC;

    float v[6]; float s = 0.f;
    #pragma unroll
    for (int j = 0; j < 6; ++j) { v[j] = in[base + lane + 32*j]; s += v[j]; }
    #pragma unroll
    for (int o = 16; o; o >>= 1) s += __shfl_xor_sync(0xffffffffu, s, o);
    float mu = s * (1.0f/192.0f);
    float vs = 0.f;
    #pragma unroll
    for (int j = 0; j < 6; ++j) { float d = v[j]-mu; vs += d*d; }
    #pragma unroll
    for (int o = 16; o; o >>= 1) vs += __shfl_xor_sync(0xffffffffu, vs, o);
    float rinv = rsqrtf(vs * (1.0f/192.0f) + 1e-5f);

    size_t obase;
    if (windowed) {
        int w = token & 127, h = (token >> 7) & 127, t = (token >> 14) & 7, bb = token >> 17;
        int win = ((bb*4 + (t >> 1))*16 + (h >> 3))*16 + (w >> 3);
        int n   = ((t & 1) << 6) | ((h & 7) << 3) | (w & 7);
        obase = ((size_t)win * NWTOK + n) * CC;
    } else obase = base;
    #pragma unroll
    for (int j = 0; j < 6; ++j) {
        int c = lane + 32*j;
        out[obase + c] = __float2half_rn((v[j]-mu)*rinv*g[c] + b[c]);
    }
}

// ---------------- fp32 -> fp16 weight conversion ----------------
__global__ void cvt_half_kernel(const float* __restrict__ in, __half* __restrict__ out, int n) {
    int i = blockIdx.x * 256 + threadIdx.x;
    if (i < n) out[i] = __float2half_rn(in[i]);
}

// ---------------- expand relative-position bias: [head][n][m] -------------
__global__ void bias_expand_kernel(const float* __restrict__ bt, float* __restrict__ bf) {
    int idx = blockIdx.x * 256 + threadIdx.x;
    if (idx >= HEADS*NWTOK*NWTOK) return;
    int h = idx >> 14, rem = idx & 16383, n = rem >> 7, m = rem & 127;
    int t1 = n >> 6, h1 = (n >> 3) & 7, w1 = n & 7;
    int t2 = m >> 6, h2 = (m >> 3) & 7, w2 = m & 7;
    int bi = (t1 - t2 + 1)*225 + (h1 - h2 + 7)*15 + (w1 - w2 + 7);
    bf[idx] = bt[bi*HEADS + h];
}

// ---------------- fp16 mma GEMM: out[M,N]=A[M,K]@W[N,K]^T + bias -----------
// modes: 0 plain->half  1 GELU->half  2 +resid->f32  3 +win-reverse +resid->f32
#define BM 128
#define BN 192
#define BK 32                               // halves per K chunk
#define PADH 40                             // halves per smem row (80B)
#define STG_BYTES ((BM + BN) * PADH * 2)    // 25600
#define GSMEM (2*STG_BYTES)                 // 51200

__device__ __forceinline__ void load_tiles(const __half* __restrict__ A, const __half* __restrict__ W,
                                           int K, int row0, int col0, int kt,
                                           __half* sA, __half* sB, int tid)
{
    uint32_t aA = smem_u32(sA), aB = smem_u32(sB);
    #pragma unroll
    for (int j = 0; j < 2; ++j) {            // A: 128 rows x 4 x 16B
        int idx = tid + j*256;
        int r = idx >> 2, c4 = idx & 3;
        cp_async16(aA + (uint32_t)(r*PADH + c4*8)*2, A + (size_t)(row0 + r)*K + kt + c4*8);
    }
    #pragma unroll
    for (int j = 0; j < 3; ++j) {            // B: 192 rows x 4 x 16B
        int idx = tid + j*256;
        int r = idx >> 2, c4 = idx & 3;
        cp_async16(aB + (uint32_t)(r*PADH + c4*8)*2, W + (size_t)(col0 + r)*K + kt + c4*8);
    }
}

__global__ __launch_bounds__(256, 1)
void gemm_mma(const __half* __restrict__ A, const __half* __restrict__ W,
              const float* __restrict__ bias, void* __restrict__ outv,
              int N, int K, int mode, const float* __restrict__ resid)
{
    extern __shared__ __half smh[];
    __half* sA[2] = { smh,            smh + STG_BYTES/2 };

    int tid = threadIdx.x;
    int lane = tid & 31, wid = tid >> 5;
    int warp_m = wid & 1, warp_n = wid >> 1;       // 2 x 4 warps, warp tile 64x48
    int col0 = blockIdx.x * BN;                    // col = x for L2 A-reuse
    int row0 = blockIdx.y * BM;
    int NC = K / BK;

    float acc[4][6][4];
    #pragma unroll
    for (int i = 0; i < 4; ++i)
        #pragma unroll
        for (int j = 0; j < 6; ++j)
            #pragma unroll
            for (int k = 0; k < 4; ++k) acc[i][j][k] = 0.f;

    int r0 = lane >> 2, c0 = lane & 3;

    // ldmatrix per-lane offsets (bytes within stage)
    int arow  = (lane & 7) + 8*((lane >> 3) & 1);  // 0..15 within 16-row tile
    int akoff = (lane >> 4) * 8;                   // 0 or 8 halves
    uint32_t aoff[4];
    #pragma unroll
    for (int mf = 0; mf < 4; ++mf)
        aoff[mf] = (uint32_t)(((warp_m*64 + mf*16 + arow)*PADH + akoff) * 2);
    int bmat   = lane >> 3;                        // matrix index 0..3
    int brow   = lane & 7;
    int bnhalf = bmat >> 1;                        // 0/1 -> nf offset
    int bkoff  = (bmat & 1) * 8;                   // 0 or 8 halves
    uint32_t boff[3];
    #pragma unroll
    for (int j = 0; j < 3; ++j)
        boff[j] = (uint32_t)(BM*PADH*2 +
                  ((warp_n*48 + (2*j + bnhalf)*8 + brow)*PADH + bkoff) * 2);

    load_tiles(A, W, K, row0, col0, 0, sA[0], sA[0] + BM*PADH, tid);
    cp_commit();

    for (int i = 0; i < NC; ++i) {
        __syncthreads();
        if (i + 1 < NC)
            load_tiles(A, W, K, row0, col0, (i+1)*BK,
                       sA[(i+1)&1], sA[(i+1)&1] + BM*PADH, tid);
        cp_commit();
        cp_wait1();
        __syncthreads();

        uint32_t base = smem_u32(sA[i & 1]);

        #pragma unroll
        for (int kk = 0; kk < 2; ++kk) {
            uint32_t kb = kk*16*2;                 // k16 step in bytes
            uint32_t af[4][4], bf[6][2];
            #pragma unroll
            for (int mf = 0; mf < 4; ++mf)
                ldsm_x4(af[mf], base + aoff[mf] + kb);
            #pragma unroll
            for (int j = 0; j < 3; ++j) {
                uint32_t br[4];
                ldsm_x4(br, base + boff[j] + kb);
                bf[2*j  ][0] = br[0]; bf[2*j  ][1] = br[1];
                bf[2*j+1][0] = br[2]; bf[2*j+1][1] = br[3];
            }
            #pragma unroll
            for (int mf = 0; mf < 4; ++mf)
                #pragma unroll
                for (int nf = 0; nf < 6; ++nf)
                    mma_f16(acc[mf][nf], af[mf], bf[nf]);
        }
    }

    // ---------------- epilogue ----------------
    #pragma unroll
    for (int mf = 0; mf < 4; ++mf) {
        #pragma unroll
        for (int half = 0; half < 2; ++half) {
            int gm = row0 + warp_m*64 + mf*16 + half*8 + r0;
            size_t rowbase;
            if (mode == 3) {
                int win = gm >> 7, n = gm & 127;
                int bb = win >> 10, rem = win & 1023;
                int t = (rem >> 8)*2 + (n >> 6);
                int h = ((rem >> 4) & 15)*8 + ((n >> 3) & 7);
                int w = (rem & 15)*8 + (n & 7);
                rowbase = (size_t)(((bb*TT + t)*HH + h)*WWD + w) * CC;
            } else {
                rowbase = (size_t)gm * N;
            }
            #pragma unroll
            for (int nf = 0; nf < 6; ++nf) {
                int gn = col0 + warp_n*48 + nf*8 + c0*2;
                float v0 = acc[mf][nf][half*2 + 0] + bias[gn];
                float v1 = acc[mf][nf][half*2 + 1] + bias[gn + 1];
                if (mode == 0) {
                    *(__half2*)((__half*)outv + rowbase + gn) = __floats2half2_rn(v0, v1);
                } else if (mode == 1) {
                    *(__half2*)((__half*)outv + rowbase + gn) =
                        __floats2half2_rn(gelu_exact(v0), gelu_exact(v1));
                } else {
                    const float2 rr = *(const float2*)(resid + rowbase + gn);
                    float2 o; o.x = v0 + rr.x; o.y = v1 + rr.y;
                    *(float2*)((float*)outv + rowbase + gn) = o;
                }
            }
        }
    }
}

// ---------------- attention via fp16 mma ------------------------------------
// one block per (head, window); 4 warps.
// halves: Ps 128x136 (overlays Qs 128x40 + Ks 128x40), Vts 32x136
#define PQH 40
#define PPH 136
#define ATT_SMEM ((128*PPH + 32*PPH)*2)     // 43520 bytes

__global__ __launch_bounds__(128)
void attn_mma(const __half* __restrict__ qkv,
              const float* __restrict__ biasf,
              __half* __restrict__ outp)
{
    extern __shared__ __half sh[];
    __half* Ps  = sh;                    // 128*136
    __half* Qs  = sh;                    // overlay
    __half* Ks  = sh + 128*PQH;          // overlay (ends at 10240 halves < 128*136)
    __half* Vts = sh + 128*PPH;          // 32*136

    int head = blockIdx.x, win = blockIdx.y;
    int tid = threadIdx.x, lane = tid & 31, w = tid >> 5;
    int r0 = lane >> 2, c0 = lane & 3;

    // ---- stage Q, K (full 32 halves each) and V^T ----
    {
        const __half* rb = qkv + (size_t)win*NWTOK*QKVDIM + (size_t)tid*QKVDIM + head*HDIM;
        const uint4* q4 = (const uint4*)(rb);
        const uint4* k4 = (const uint4*)(rb + CC);
        const uint4* v4 = (const uint4*)(rb + 2*CC);
        uint4* qd = (uint4*)(Qs + tid*PQH);
        uint4* kd = (uint4*)(Ks + tid*PQH);
        qd[0] = q4[0]; qd[1] = q4[1]; qd[2] = q4[2]; qd[3] = q4[3];
        kd[0] = k4[0]; kd[1] = k4[1]; kd[2] = k4[2]; kd[3] = k4[3];
        uint4 va = v4[0], vb = v4[1], vc = v4[2], vd2 = v4[3];
        const __half* vh = (const __half*)&va;
        #pragma unroll
        for (int d = 0; d < 8; ++d) Vts[d*PPH + tid] = vh[d];
        vh = (const __half*)&vb;
        #pragma unroll
        for (int d = 0; d < 8; ++d) Vts[(d+8)*PPH + tid] = vh[d];
        vh = (const __half*)&vc;
        #pragma unroll
        for (int d = 0; d < 8; ++d) Vts[(d+16)*PPH + tid] = vh[d];
        vh = (const __half*)&vd2;
        #pragma unroll
        for (int d = 0; d < 8; ++d) Vts[(d+24)*PPH + tid] = vh[d];
    }
    __syncthreads();

    // ---- S = Q K^T (unscaled; scale folded into bias step) ----
    float s[2][16][4];
    #pragma unroll
    for (int a = 0; a < 2; ++a)
        #pragma unroll
        for (int b = 0; b < 16; ++b)
            #pragma unroll
            for (int c = 0; c < 4; ++c) s[a][b][c] = 0.f;

    {
        const __half* aq = Qs + (w*32 + r0)*PQH + 2*c0;
        const __half* bk = Ks + r0*PQH + 2*c0;
        #pragma unroll
        for (int kk = 0; kk < 2; ++kk) {
            int k0 = kk*16;
            uint32_t af[2][4];
            #pragma unroll
            for (int mf = 0; mf < 2; ++mf) {
                af[mf][0] = ldh2(aq + (mf*16    )*PQH + k0    );
                af[mf][1] = ldh2(aq + (mf*16 + 8)*PQH + k0    );
                af[mf][2] = ldh2(aq + (mf*16    )*PQH + k0 + 8);
                af[mf][3] = ldh2(aq + (mf*16 + 8)*PQH + k0 + 8);
            }
            #pragma unroll
            for (int nf = 0; nf < 16; ++nf) {
                uint32_t bf[2];
                bf[0] = ldh2(bk + nf*8*PQH + k0    );
                bf[1] = ldh2(bk + nf*8*PQH + k0 + 8);
                mma_f16(s[0][nf], af[0], bf);
                mma_f16(s[1][nf], af[1], bf);
            }
        }
    }

    // ---- scale + bias + row softmax (normalization deferred) ----
    float inv[2][2];
    const float* bh = biasf + (size_t)head*NWTOK*NWTOK;
    #pragma unroll
    for (int mf = 0; mf < 2; ++mf) {
        #pragma unroll
        for (int half = 0; half < 2; ++half) {
            int r = w*32 + mf*16 + half*8 + r0;
            const float2* brow = (const float2*)(bh + r*NWTOK) + c0;
            float mx = -1e30f;
            #pragma unroll
            for (int nf = 0; nf < 16; ++nf) {
                float2 bb = brow[nf*4];
                float v0 = s[mf][nf][half*2+0]*ATTSCALE + bb.x;
                float v1 = s[mf][nf][half*2+1]*ATTSCALE + bb.y;
                s[mf][nf][half*2+0] = v0;
                s[mf][nf][half*2+1] = v1;
                mx = fmaxf(mx, fmaxf(v0, v1));
            }
            mx = fmaxf(mx, __shfl_xor_sync(0xffffffffu, mx, 1));
            mx = fmaxf(mx, __shfl_xor_sync(0xffffffffu, mx, 2));
            float sum = 0.f;
            #pragma unroll
            for (int nf = 0; nf < 16; ++nf) {
                float e0 = __expf(s[mf][nf][half*2+0] - mx);
                float e1 = __expf(s[mf][nf][half*2+1] - mx);
                s[mf][nf][half*2+0] = e0;
                s[mf][nf][half*2+1] = e1;
                sum += e0 + e1;
            }
            sum += __shfl_xor_sync(0xffffffffu, sum, 1);
            sum += __shfl_xor_sync(0xffffffffu, sum, 2);
            inv[mf][half] = 1.0f / sum;
        }
    }

    __syncthreads();   // all warps done reading Qs/Ks before P overwrites

    // ---- store P (half) ----
    #pragma unroll
    for (int mf = 0; mf < 2; ++mf) {
        #pragma unroll
        for (int half = 0; half < 2; ++half) {
            int r = w*32 + mf*16 + half*8 + r0;
            __half* pr = Ps + r*PPH + 2*c0;
            #pragma unroll
            for (int nf = 0; nf < 16; ++nf)
                *(__half2*)(pr + nf*8) =
                    __floats2half2_rn(s[mf][nf][half*2+0], s[mf][nf][half*2+1]);
        }
    }
    __syncthreads();

    // ---- O = P V ----
    float o[2][4][4];
    #pragma unroll
    for (int a = 0; a < 2; ++a)
        #pragma unroll
        for (int b = 0; b < 4; ++b)
            #pragma unroll
            for (int c = 0; c < 4; ++c) o[a][b][c] = 0.f;

    {
        const __half* ap = Ps + (w*32 + r0)*PPH + 2*c0;
        const __half* bv = Vts + r0*PPH + 2*c0;
        #pragma unroll
        for (int kk = 0; kk < 8; ++kk) {
            int k0 = kk*16;
            uint32_t af[2][4];
            #pragma unroll
            for (int mf = 0; mf < 2; ++mf) {
                af[mf][0] = ldh2(ap + (mf*16    )*PPH + k0    );
                af[mf][1] = ldh2(ap + (mf*16 + 8)*PPH + k0    );
                af[mf][2] = ldh2(ap + (mf*16    )*PPH + k0 + 8);
                af[mf][3] = ldh2(ap + (mf*16 + 8)*PPH + k0 + 8);
            }
            #pragma unroll
            for (int nf = 0; nf < 4; ++nf) {
                uint32_t bf[2];
                bf[0] = ldh2(bv + nf*8*PPH + k0    );
                bf[1] = ldh2(bv + nf*8*PPH + k0 + 8);
                mma_f16(o[0][nf], af[0], bf);
                mma_f16(o[1][nf], af[1], bf);
            }
        }
    }

    // ---- epilogue: normalize + store half ----
    #pragma unroll
    for (int mf = 0; mf < 2; ++mf) {
        #pragma unroll
        for (int half = 0; half < 2; ++half) {
            int r = w*32 + mf*16 + half*8 + r0;
            float sc = inv[mf][half];
            __half* op = outp + ((size_t)win*NWTOK + r)*CC + head*HDIM;
            #pragma unroll
            for (int nf = 0; nf < 4; ++nf)
                *(__half2*)(op + nf*8 + 2*c0) =
                    __floats2half2_rn(o[mf][nf][half*2+0]*sc, o[mf][nf][half*2+1]*sc);
        }
    }
}

// ---------------- launch ----------------
extern "C" void kernel_launch(void* const* d_in, const int* in_sizes, int n_in,
                              void* d_out, int out_size)
{
    const float* x        = (const float*)d_in[0];
    const float* norm1_g  = (const float*)d_in[1];
    const float* norm1_b  = (const float*)d_in[2];
    const float* qkv_w    = (const float*)d_in[3];
    const float* qkv_b    = (const float*)d_in[4];
    const float* bias_tab = (const float*)d_in[5];
    const float* proj_w   = (const float*)d_in[6];
    const float* proj_b   = (const float*)d_in[7];
    const float* norm2_g  = (const float*)d_in[8];
    const float* norm2_b  = (const float*)d_in[9];
    const float* fc1_w    = (const float*)d_in[10];
    const float* fc1_b    = (const float*)d_in[11];
    const float* fc2_w    = (const float*)d_in[12];
    const float* fc2_b    = (const float*)d_in[13];
    float* out = (float*)d_out;

    __half *xw, *qkvb, *attno, *h1, *wq, *wp, *w1, *w2;
    float *x2, *bf;
    cudaGetSymbolAddress((void**)&xw,    g_xw);
    cudaGetSymbolAddress((void**)&qkvb,  g_qkv);
    cudaGetSymbolAddress((void**)&attno, g_attnout);
    cudaGetSymbolAddress((void**)&x2,    g_x2);
    cudaGetSymbolAddress((void**)&h1,    g_h1);
    cudaGetSymbolAddress((void**)&wq,    g_wq);
    cudaGetSymbolAddress((void**)&wp,    g_wp);
    cudaGetSymbolAddress((void**)&w1,    g_w1);
    cudaGetSymbolAddress((void**)&w2,    g_w2);
    cudaGetSymbolAddress((void**)&bf,    g_biasf);

    cudaFuncSetAttribute(attn_mma, cudaFuncAttributeMaxDynamicSharedMemorySize, ATT_SMEM);
    cudaFuncSetAttribute(gemm_mma, cudaFuncAttributeMaxDynamicSharedMemorySize, GSMEM);

    // weight conversion + bias expansion
    cvt_half_kernel<<<(QKVDIM*CC+255)/256, 256>>>(qkv_w, wq, QKVDIM*CC);
    cvt_half_kernel<<<(CC*CC+255)/256,     256>>>(proj_w, wp, CC*CC);
    cvt_half_kernel<<<(HIDDEN*CC+255)/256, 256>>>(fc1_w, w1, HIDDEN*CC);
    cvt_half_kernel<<<(CC*HIDDEN+255)/256, 256>>>(fc2_w, w2, CC*HIDDEN);
    bias_expand_kernel<<<(HEADS*NWTOK*NWTOK+255)/256, 256>>>(bias_tab, bf);

    // 1. LN1 + window partition -> half
    ln_kernel<<<TOKENS/8, 256>>>(x, norm1_g, norm1_b, xw, 1);
    // 2. QKV GEMM -> half
    gemm_mma<<<dim3(QKVDIM/BN, TOKENS/BM), 256, GSMEM>>>(xw, wq, qkv_b, qkvb, QKVDIM, CC, 0, nullptr);
    // 3. windowed attention -> half
    attn_mma<<<dim3(HEADS, NWIN), 128, ATT_SMEM>>>(qkvb, bf, attno);
    // 4. proj + window-reverse + residual -> f32
    gemm_mma<<<dim3(CC/BN, TOKENS/BM), 256, GSMEM>>>(attno, wp, proj_b, x2, CC, CC, 3, x);
    // 5. LN2 -> half
    ln_kernel<<<TOKENS/8, 256>>>(x2, norm2_g, norm2_b, xw, 0);
    // 6. FC1 + GELU -> half
    gemm_mma<<<dim3(HIDDEN/BN, TOKENS/BM), 256, GSMEM>>>(xw, w1, fc1_b, h1, HIDDEN, CC, 1, nullptr);
    // 7. FC2 + residual -> out (f32)
    gemm_mma<<<dim3(CC/BN, TOKENS/BM), 256, GSMEM>>>(h1, w2, fc2_b, out, CC, HIDDEN, 2, x2);
}

// round 9
// speedup vs baseline: 4.6581x; 1.0508x over previous
#include <cuda_runtime.h>
#include <cuda_fp16.h>
#include <math.h>
#include <stdint.h>

// ---------------- problem constants ----------------
#define BATCH 2
#define TT 8
#define HH 128
#define WWD 128
#define CC 192
#define TOKENS (BATCH*TT*HH*WWD)         // 262144
#define NWIN 2048
#define NWTOK 128
#define HEADS 6
#define HDIM 32
#define HIDDEN 768
#define QKVDIM 576
#define ATTSCALE 0.17677669529663687f

// ---------------- scratch ----------------
__device__ __half g_xw[(size_t)TOKENS * CC];
__device__ __half g_qkv[(size_t)NWIN * NWTOK * QKVDIM];
__device__ __half g_attnout[(size_t)TOKENS * CC];
__device__ float  g_x2[(size_t)TOKENS * CC];
__device__ __half g_h1[(size_t)TOKENS * HIDDEN];
__device__ __half g_wq[QKVDIM * CC];
__device__ __half g_wp[CC * CC];
__device__ __half g_w1[HIDDEN * CC];
__device__ __half g_w2[CC * HIDDEN];
__device__ float  g_biasf[HEADS * NWTOK * NWTOK];

// ---------------- helpers ----------------
__device__ __forceinline__ void cp_async16(uint32_t dst, const void* src) {
    asm volatile("cp.async.cg.shared.global [%0], [%1], 16;" :: "r"(dst), "l"(src));
}
__device__ __forceinline__ void cp_commit() { asm volatile("cp.async.commit_group;"); }
__device__ __forceinline__ void cp_wait1()  { asm volatile("cp.async.wait_group 1;"); }
__device__ __forceinline__ uint32_t smem_u32(const void* p) {
    uint32_t a;
    asm("{ .reg .u64 t; cvta.to.shared.u64 t, %1; cvt.u32.u64 %0, t; }" : "=r"(a) : "l"(p));
    return a;
}
__device__ __forceinline__ void mma_f16(float c[4], const uint32_t a[4], const uint32_t b[2]) {
    asm volatile(
        "mma.sync.aligned.m16n8k16.row.col.f32.f16.f16.f32 "
        "{%0,%1,%2,%3}, {%4,%5,%6,%7}, {%8,%9}, {%0,%1,%2,%3};"
        : "+f"(c[0]), "+f"(c[1]), "+f"(c[2]), "+f"(c[3])
        : "r"(a[0]), "r"(a[1]), "r"(a[2]), "r"(a[3]), "r"(b[0]), "r"(b[1]));
}
__device__ __forceinline__ void ldsm_x4(uint32_t r[4], uint32_t addr) {
    asm volatile("ldmatrix.sync.aligned.m8n8.x4.shared.b16 {%0,%1,%2,%3}, [%4];"
        : "=r"(r[0]), "=r"(r[1]), "=r"(r[2]), "=r"(r[3]) : "r"(addr));
}
__device__ __forceinline__ float gelu_exact(float x) {
    return 0.5f * x * (1.0f + erff(x * 0.70710678118654752f));
}
__device__ __forceinline__ uint32_t ldh2(const __half* p) { return *(const uint32_t*)p; }

// ---------------- LayerNorm -> half (window scatter) ------------------------
__global__ void ln_kernel(const float* __restrict__ in,
                          const float* __restrict__ g,
                          const float* __restrict__ b,
                          __half* __restrict__ out, int windowed)
{
    int token = (blockIdx.x << 3) + (threadIdx.x >> 5);
    int lane  = threadIdx.x & 31;
    size_t base = (size_t)token * CC;

    float v[6]; float s = 0.f;
    #pragma unroll
    for (int j = 0; j < 6; ++j) { v[j] = in[base + lane + 32*j]; s += v[j]; }
    #pragma unroll
    for (int o = 16; o; o >>= 1) s += __shfl_xor_sync(0xffffffffu, s, o);
    float mu = s * (1.0f/192.0f);
    float vs = 0.f;
    #pragma unroll
    for (int j = 0; j < 6; ++j) { float d = v[j]-mu; vs += d*d; }
    #pragma unroll
    for (int o = 16; o; o >>= 1) vs += __shfl_xor_sync(0xffffffffu, vs, o);
    float rinv = rsqrtf(vs * (1.0f/192.0f) + 1e-5f);

    size_t obase;
    if (windowed) {
        int w = token & 127, h = (token >> 7) & 127, t = (token >> 14) & 7, bb = token >> 17;
        int win = ((bb*4 + (t >> 1))*16 + (h >> 3))*16 + (w >> 3);
        int n   = ((t & 1) << 6) | ((h & 7) << 3) | (w & 7);
        obase = ((size_t)win * NWTOK + n) * CC;
    } else obase = base;
    #pragma unroll
    for (int j = 0; j < 6; ++j) {
        int c = lane + 32*j;
        out[obase + c] = __float2half_rn((v[j]-mu)*rinv*g[c] + b[c]);
    }
}

// ---------------- merged setup: weight conversions + bias expansion --------
#define NWQ (QKVDIM*CC)
#define NWP (CC*CC)
#define NW1 (HIDDEN*CC)
#define NW2 (CC*HIDDEN)
#define NBF (HEADS*NWTOK*NWTOK)
#define NSETUP (NWQ+NWP+NW1+NW2+NBF)

__global__ void setup_kernel(const float* __restrict__ qkv_w, const float* __restrict__ proj_w,
                             const float* __restrict__ fc1_w, const float* __restrict__ fc2_w,
                             const float* __restrict__ bt,
                             __half* __restrict__ wq, __half* __restrict__ wp,
                             __half* __restrict__ w1, __half* __restrict__ w2,
                             float* __restrict__ bf)
{
    int i = blockIdx.x * 256 + threadIdx.x;
    if (i < NWQ) { wq[i] = __float2half_rn(qkv_w[i]); return; }
    i -= NWQ;
    if (i < NWP) { wp[i] = __float2half_rn(proj_w[i]); return; }
    i -= NWP;
    if (i < NW1) { w1[i] = __float2half_rn(fc1_w[i]); return; }
    i -= NW1;
    if (i < NW2) { w2[i] = __float2half_rn(fc2_w[i]); return; }
    i -= NW2;
    if (i < NBF) {
        int h = i >> 14, rem = i & 16383, n = rem >> 7, m = rem & 127;
        int t1 = n >> 6, h1 = (n >> 3) & 7, w1i = n & 7;
        int t2 = m >> 6, h2 = (m >> 3) & 7, w2i = m & 7;
        int bi = (t1 - t2 + 1)*225 + (h1 - h2 + 7)*15 + (w1i - w2i + 7);
        bf[i] = bt[bi*HEADS + h];
    }
}

// ---------------- fp16 mma GEMM: out[M,N]=A[M,K]@W[N,K]^T + bias -----------
// modes: 0 plain->half  1 GELU->half  2 +resid->f32
//        3 +win-reverse +resid->f32 x2  AND fused LN2 -> half xw
#define BM 128
#define BN 192
#define BK 64                               // halves per K chunk
#define PADH 72                             // halves per smem row (144B)
#define STG_HALVES ((BM + BN) * PADH)       // 23040
#define GSMEM (2*STG_HALVES*2)              // 92160 bytes

__device__ __forceinline__ void load_tiles(const __half* __restrict__ A, const __half* __restrict__ W,
                                           int K, int row0, int col0, int kt,
                                           __half* sA, __half* sB, int tid)
{
    uint32_t aA = smem_u32(sA), aB = smem_u32(sB);
    #pragma unroll
    for (int j = 0; j < 4; ++j) {            // A: 128 rows x 8 x 16B
        int idx = tid + j*256;
        int r = idx >> 3, c8 = idx & 7;
        cp_async16(aA + (uint32_t)(r*PADH + c8*8)*2, A + (size_t)(row0 + r)*K + kt + c8*8);
    }
    #pragma unroll
    for (int j = 0; j < 6; ++j) {            // B: 192 rows x 8 x 16B
        int idx = tid + j*256;
        int r = idx >> 3, c8 = idx & 7;
        cp_async16(aB + (uint32_t)(r*PADH + c8*8)*2, W + (size_t)(col0 + r)*K + kt + c8*8);
    }
}

__global__ __launch_bounds__(256, 1)
void gemm_mma(const __half* __restrict__ A, const __half* __restrict__ W,
              const float* __restrict__ bias, void* __restrict__ outv,
              int N, int K, int mode, const float* __restrict__ resid,
              const float* __restrict__ g2, const float* __restrict__ b2,
              __half* __restrict__ xw_out)
{
    extern __shared__ __half smh[];
    __half* sA[2] = { smh, smh + STG_HALVES };

    int tid = threadIdx.x;
    int lane = tid & 31, wid = tid >> 5;
    int warp_m = wid & 1, warp_n = wid >> 1;       // 2 x 4 warps, warp tile 64x48
    int col0 = blockIdx.x * BN;                    // col = x for L2 A-reuse
    int row0 = blockIdx.y * BM;
    int NC = K / BK;

    float acc[4][6][4];
    #pragma unroll
    for (int i = 0; i < 4; ++i)
        #pragma unroll
        for (int j = 0; j < 6; ++j)
            #pragma unroll
            for (int k = 0; k < 4; ++k) acc[i][j][k] = 0.f;

    int r0 = lane >> 2, c0 = lane & 3;

    // ldmatrix per-lane offsets (bytes within stage)
    int arow  = (lane & 7) + 8*((lane >> 3) & 1);
    int akoff = (lane >> 4) * 8;
    uint32_t aoff[4];
    #pragma unroll
    for (int mf = 0; mf < 4; ++mf)
        aoff[mf] = (uint32_t)(((warp_m*64 + mf*16 + arow)*PADH + akoff) * 2);
    int bmat   = lane >> 3;
    int brow   = lane & 7;
    int bnhalf = bmat >> 1;
    int bkoff  = (bmat & 1) * 8;
    uint32_t boff[3];
    #pragma unroll
    for (int j = 0; j < 3; ++j)
        boff[j] = (uint32_t)(BM*PADH*2 +
                  ((warp_n*48 + (2*j + bnhalf)*8 + brow)*PADH + bkoff) * 2);

    load_tiles(A, W, K, row0, col0, 0, sA[0], sA[0] + BM*PADH, tid);
    cp_commit();

    for (int i = 0; i < NC; ++i) {
        __syncthreads();
        if (i + 1 < NC)
            load_tiles(A, W, K, row0, col0, (i+1)*BK,
                       sA[(i+1)&1], sA[(i+1)&1] + BM*PADH, tid);
        cp_commit();
        cp_wait1();
        __syncthreads();

        uint32_t base = smem_u32(sA[i & 1]);

        #pragma unroll
        for (int kk = 0; kk < 4; ++kk) {
            uint32_t kb = kk*16*2;
            uint32_t af[4][4], bf[6][2];
            #pragma unroll
            for (int mf = 0; mf < 4; ++mf)
                ldsm_x4(af[mf], base + aoff[mf] + kb);
            #pragma unroll
            for (int j = 0; j < 3; ++j) {
                uint32_t br[4];
                ldsm_x4(br, base + boff[j] + kb);
                bf[2*j  ][0] = br[0]; bf[2*j  ][1] = br[1];
                bf[2*j+1][0] = br[2]; bf[2*j+1][1] = br[3];
            }
            #pragma unroll
            for (int mf = 0; mf < 4; ++mf)
                #pragma unroll
                for (int nf = 0; nf < 6; ++nf)
                    mma_f16(acc[mf][nf], af[mf], bf[nf]);
        }
    }

    // ---------------- epilogue ----------------
    if (mode != 3) {
        #pragma unroll
        for (int mf = 0; mf < 4; ++mf) {
            #pragma unroll
            for (int half = 0; half < 2; ++half) {
                int gm = row0 + warp_m*64 + mf*16 + half*8 + r0;
                size_t rowbase = (size_t)gm * N;
                #pragma unroll
                for (int nf = 0; nf < 6; ++nf) {
                    int gn = col0 + warp_n*48 + nf*8 + c0*2;
                    float v0 = acc[mf][nf][half*2 + 0] + bias[gn];
                    float v1 = acc[mf][nf][half*2 + 1] + bias[gn + 1];
                    if (mode == 0) {
                        *(__half2*)((__half*)outv + rowbase + gn) = __floats2half2_rn(v0, v1);
                    } else if (mode == 1) {
                        *(__half2*)((__half*)outv + rowbase + gn) =
                            __floats2half2_rn(gelu_exact(v0), gelu_exact(v1));
                    } else {
                        const float2 rr = *(const float2*)(resid + rowbase + gn);
                        float2 o; o.x = v0 + rr.x; o.y = v1 + rr.y;
                        *(float2*)((float*)outv + rowbase + gn) = o;
                    }
                }
            }
        }
        return;
    }

    // ---- mode 3: x2 = attn_proj + bias + shortcut, THEN fused LN2 -> xw ----
    __syncthreads();                      // mainloop smem dead; reuse for reductions
    float* redsum = (float*)smh;          // [128]
    float* redsq  = (float*)smh + 128;    // [128]
    if (tid < 128) { redsum[tid] = 0.f; redsq[tid] = 0.f; }
    __syncthreads();

    int toks[4][2];
    #pragma unroll
    for (int mf = 0; mf < 4; ++mf) {
        #pragma unroll
        for (int half = 0; half < 2; ++half) {
            int gm = row0 + warp_m*64 + mf*16 + half*8 + r0;
            int win = gm >> 7, n = gm & 127;
            int bb = win >> 10, rem = win & 1023;
            int t = (rem >> 8)*2 + (n >> 6);
            int h = ((rem >> 4) & 15)*8 + ((n >> 3) & 7);
            int w = (rem & 15)*8 + (n & 7);
            int token = ((bb*TT + t)*HH + h)*WWD + w;
            toks[mf][half] = token;
            size_t rowbase = (size_t)token * CC;

            float psum = 0.f, psq = 0.f;
            #pragma unroll
            for (int nf = 0; nf < 6; ++nf) {
                int gn = col0 + warp_n*48 + nf*8 + c0*2;
                const float2 rr = *(const float2*)(resid + rowbase + gn);
                float v0 = acc[mf][nf][half*2+0] + bias[gn]   + rr.x;
                float v1 = acc[mf][nf][half*2+1] + bias[gn+1] + rr.y;
                acc[mf][nf][half*2+0] = v0;
                acc[mf][nf][half*2+1] = v1;
                float2 o; o.x = v0; o.y = v1;
                *(float2*)((float*)outv + rowbase + gn) = o;
                psum += v0 + v1;
                psq  += v0*v0 + v1*v1;
            }
            // quad reduce (lanes differ only in c0)
            psum += __shfl_xor_sync(0xffffffffu, psum, 1);
            psum += __shfl_xor_sync(0xffffffffu, psum, 2);
            psq  += __shfl_xor_sync(0xffffffffu, psq, 1);
            psq  += __shfl_xor_sync(0xffffffffu, psq, 2);
            if (c0 == 0) {
                int lr = warp_m*64 + mf*16 + half*8 + r0;
                atomicAdd(&redsum[lr], psum);
                atomicAdd(&redsq[lr],  psq);
            }
        }
    }
    __syncthreads();

    #pragma unroll
    for (int mf = 0; mf < 4; ++mf) {
        #pragma unroll
        for (int half = 0; half < 2; ++half) {
            int lr = warp_m*64 + mf*16 + half*8 + r0;
            float mu  = redsum[lr] * (1.0f/192.0f);
            float var = redsq[lr] * (1.0f/192.0f) - mu*mu;
            float rinv = rsqrtf(var + 1e-5f);
            size_t rowbase = (size_t)toks[mf][half] * CC;
            #pragma unroll
            for (int nf = 0; nf < 6; ++nf) {
                int gn = col0 + warp_n*48 + nf*8 + c0*2;
                float n0 = (acc[mf][nf][half*2+0] - mu)*rinv*g2[gn]   + b2[gn];
                float n1 = (acc[mf][nf][half*2+1] - mu)*rinv*g2[gn+1] + b2[gn+1];
                *(__half2*)(xw_out + rowbase + gn) = __floats2half2_rn(n0, n1);
            }
        }
    }
}

// ---------------- attention via fp16 mma ------------------------------------
#define PQH 40
#define PPH 136
#define ATT_SMEM ((128*PPH + 32*PPH)*2)     // 43520 bytes

__global__ __launch_bounds__(128)
void attn_mma(const __half* __restrict__ qkv,
              const float* __restrict__ biasf,
              __half* __restrict__ outp)
{
    extern __shared__ __half sh[];
    __half* Ps  = sh;
    __half* Qs  = sh;
    __half* Ks  = sh + 128*PQH;
    __half* Vts = sh + 128*PPH;

    int head = blockIdx.x, win = blockIdx.y;
    int tid = threadIdx.x, lane = tid & 31, w = tid >> 5;
    int r0 = lane >> 2, c0 = lane & 3;

    {
        const __half* rb = qkv + (size_t)win*NWTOK*QKVDIM + (size_t)tid*QKVDIM + head*HDIM;
        const uint4* q4 = (const uint4*)(rb);
        const uint4* k4 = (const uint4*)(rb + CC);
        const uint4* v4 = (const uint4*)(rb + 2*CC);
        uint4* qd = (uint4*)(Qs + tid*PQH);
        uint4* kd = (uint4*)(Ks + tid*PQH);
        qd[0] = q4[0]; qd[1] = q4[1]; qd[2] = q4[2]; qd[3] = q4[3];
        kd[0] = k4[0]; kd[1] = k4[1]; kd[2] = k4[2]; kd[3] = k4[3];
        uint4 va = v4[0], vb = v4[1], vc = v4[2], vd2 = v4[3];
        const __half* vh = (const __half*)&va;
        #pragma unroll
        for (int d = 0; d < 8; ++d) Vts[d*PPH + tid] = vh[d];
        vh = (const __half*)&vb;
        #pragma unroll
        for (int d = 0; d < 8; ++d) Vts[(d+8)*PPH + tid] = vh[d];
        vh = (const __half*)&vc;
        #pragma unroll
        for (int d = 0; d < 8; ++d) Vts[(d+16)*PPH + tid] = vh[d];
        vh = (const __half*)&vd2;
        #pragma unroll
        for (int d = 0; d < 8; ++d) Vts[(d+24)*PPH + tid] = vh[d];
    }
    __syncthreads();

    float s[2][16][4];
    #pragma unroll
    for (int a = 0; a < 2; ++a)
        #pragma unroll
        for (int b = 0; b < 16; ++b)
            #pragma unroll
            for (int c = 0; c < 4; ++c) s[a][b][c] = 0.f;

    {
        const __half* aq = Qs + (w*32 + r0)*PQH + 2*c0;
        const __half* bk = Ks + r0*PQH + 2*c0;
        #pragma unroll
        for (int kk = 0; kk < 2; ++kk) {
            int k0 = kk*16;
            uint32_t af[2][4];
            #pragma unroll
            for (int mf = 0; mf < 2; ++mf) {
                af[mf][0] = ldh2(aq + (mf*16    )*PQH + k0    );
                af[mf][1] = ldh2(aq + (mf*16 + 8)*PQH + k0    );
                af[mf][2] = ldh2(aq + (mf*16    )*PQH + k0 + 8);
                af[mf][3] = ldh2(aq + (mf*16 + 8)*PQH + k0 + 8);
            }
            #pragma unroll
            for (int nf = 0; nf < 16; ++nf) {
                uint32_t bf[2];
                bf[0] = ldh2(bk + nf*8*PQH + k0    );
                bf[1] = ldh2(bk + nf*8*PQH + k0 + 8);
                mma_f16(s[0][nf], af[0], bf);
                mma_f16(s[1][nf], af[1], bf);
            }
        }
    }

    float inv[2][2];
    const float* bh = biasf + (size_t)head*NWTOK*NWTOK;
    #pragma unroll
    for (int mf = 0; mf < 2; ++mf) {
        #pragma unroll
        for (int half = 0; half < 2; ++half) {
            int r = w*32 + mf*16 + half*8 + r0;
            const float2* brow = (const float2*)(bh + r*NWTOK) + c0;
            float mx = -1e30f;
            #pragma unroll
            for (int nf = 0; nf < 16; ++nf) {
                float2 bb = brow[nf*4];
                float v0 = s[mf][nf][half*2+0]*ATTSCALE + bb.x;
                float v1 = s[mf][nf][half*2+1]*ATTSCALE + bb.y;
                s[mf][nf][half*2+0] = v0;
                s[mf][nf][half*2+1] = v1;
                mx = fmaxf(mx, fmaxf(v0, v1));
            }
            mx = fmaxf(mx, __shfl_xor_sync(0xffffffffu, mx, 1));
            mx = fmaxf(mx, __shfl_xor_sync(0xffffffffu, mx, 2));
            float sum = 0.f;
            #pragma unroll
            for (int nf = 0; nf < 16; ++nf) {
                float e0 = __expf(s[mf][nf][half*2+0] - mx);
                float e1 = __expf(s[mf][nf][half*2+1] - mx);
                s[mf][nf][half*2+0] = e0;
                s[mf][nf][half*2+1] = e1;
                sum += e0 + e1;
            }
            sum += __shfl_xor_sync(0xffffffffu, sum, 1);
            sum += __shfl_xor_sync(0xffffffffu, sum, 2);
            inv[mf][half] = 1.0f / sum;
        }
    }

    __syncthreads();

    #pragma unroll
    for (int mf = 0; mf < 2; ++mf) {
        #pragma unroll
        for (int half = 0; half < 2; ++half) {
            int r = w*32 + mf*16 + half*8 + r0;
            __half* pr = Ps + r*PPH + 2*c0;
            #pragma unroll
            for (int nf = 0; nf < 16; ++nf)
                *(__half2*)(pr + nf*8) =
                    __floats2half2_rn(s[mf][nf][half*2+0], s[mf][nf][half*2+1]);
        }
    }
    __syncthreads();

    float o[2][4][4];
    #pragma unroll
    for (int a = 0; a < 2; ++a)
        #pragma unroll
        for (int b = 0; b < 4; ++b)
            #pragma unroll
            for (int c = 0; c < 4; ++c) o[a][b][c] = 0.f;

    {
        const __half* ap = Ps + (w*32 + r0)*PPH + 2*c0;
        const __half* bv = Vts + r0*PPH + 2*c0;
        #pragma unroll
        for (int kk = 0; kk < 8; ++kk) {
            int k0 = kk*16;
            uint32_t af[2][4];
            #pragma unroll
            for (int mf = 0; mf < 2; ++mf) {
                af[mf][0] = ldh2(ap + (mf*16    )*PPH + k0    );
                af[mf][1] = ldh2(ap + (mf*16 + 8)*PPH + k0    );
                af[mf][2] = ldh2(ap + (mf*16    )*PPH + k0 + 8);
                af[mf][3] = ldh2(ap + (mf*16 + 8)*PPH + k0 + 8);
            }
            #pragma unroll
            for (int nf = 0; nf < 4; ++nf) {
                uint32_t bf[2];
                bf[0] = ldh2(bv + nf*8*PPH + k0    );
                bf[1] = ldh2(bv + nf*8*PPH + k0 + 8);
                mma_f16(o[0][nf], af[0], bf);
                mma_f16(o[1][nf], af[1], bf);
            }
        }
    }

    #pragma unroll
    for (int mf = 0; mf < 2; ++mf) {
        #pragma unroll
        for (int half = 0; half < 2; ++half) {
            int r = w*32 + mf*16 + half*8 + r0;
            float sc = inv[mf][half];
            __half* op = outp + ((size_t)win*NWTOK + r)*CC + head*HDIM;
            #pragma unroll
            for (int nf = 0; nf < 4; ++nf)
                *(__half2*)(op + nf*8 + 2*c0) =
                    __floats2half2_rn(o[mf][nf][half*2+0]*sc, o[mf][nf][half*2+1]*sc);
        }
    }
}

// ---------------- launch ----------------
extern "C" void kernel_launch(void* const* d_in, const int* in_sizes, int n_in,
                              void* d_out, int out_size)
{
    const float* x        = (const float*)d_in[0];
    const float* norm1_g  = (const float*)d_in[1];
    const float* norm1_b  = (const float*)d_in[2];
    const float* qkv_w    = (const float*)d_in[3];
    const float* qkv_b    = (const float*)d_in[4];
    const float* bias_tab = (const float*)d_in[5];
    const float* proj_w   = (const float*)d_in[6];
    const float* proj_b   = (const float*)d_in[7];
    const float* norm2_g  = (const float*)d_in[8];
    const float* norm2_b  = (const float*)d_in[9];
    const float* fc1_w    = (const float*)d_in[10];
    const float* fc1_b    = (const float*)d_in[11];
    const float* fc2_w    = (const float*)d_in[12];
    const float* fc2_b    = (const float*)d_in[13];
    float* out = (float*)d_out;

    __half *xw, *qkvb, *attno, *h1, *wq, *wp, *w1, *w2;
    float *x2, *bf;
    cudaGetSymbolAddress((void**)&xw,    g_xw);
    cudaGetSymbolAddress((void**)&qkvb,  g_qkv);
    cudaGetSymbolAddress((void**)&attno, g_attnout);
    cudaGetSymbolAddress((void**)&x2,    g_x2);
    cudaGetSymbolAddress((void**)&h1,    g_h1);
    cudaGetSymbolAddress((void**)&wq,    g_wq);
    cudaGetSymbolAddress((void**)&wp,    g_wp);
    cudaGetSymbolAddress((void**)&w1,    g_w1);
    cudaGetSymbolAddress((void**)&w2,    g_w2);
    cudaGetSymbolAddress((void**)&bf,    g_biasf);

    cudaFuncSetAttribute(attn_mma, cudaFuncAttributeMaxDynamicSharedMemorySize, ATT_SMEM);
    cudaFuncSetAttribute(gemm_mma, cudaFuncAttributeMaxDynamicSharedMemorySize, GSMEM);

    // merged setup
    setup_kernel<<<(NSETUP+255)/256, 256>>>(qkv_w, proj_w, fc1_w, fc2_w, bias_tab,
                                            wq, wp, w1, w2, bf);

    // 1. LN1 + window partition -> half
    ln_kernel<<<TOKENS/8, 256>>>(x, norm1_g, norm1_b, xw, 1);
    // 2. QKV GEMM -> half
    gemm_mma<<<dim3(QKVDIM/BN, TOKENS/BM), 256, GSMEM>>>(xw, wq, qkv_b, qkvb,
        QKVDIM, CC, 0, nullptr, nullptr, nullptr, nullptr);
    // 3. windowed attention -> half
    attn_mma<<<dim3(HEADS, NWIN), 128, ATT_SMEM>>>(qkvb, bf, attno);
    // 4. proj + window-reverse + residual -> x2 (f32), fused LN2 -> xw (half)
    gemm_mma<<<dim3(CC/BN, TOKENS/BM), 256, GSMEM>>>(attno, wp, proj_b, x2,
        CC, CC, 3, x, norm2_g, norm2_b, xw);
    // 5. FC1 + GELU -> half
    gemm_mma<<<dim3(HIDDEN/BN, TOKENS/BM), 256, GSMEM>>>(xw, w1, fc1_b, h1,
        HIDDEN, CC, 1, nullptr, nullptr, nullptr, nullptr);
    // 6. FC2 + residual -> out (f32)
    gemm_mma<<<dim3(CC/BN, TOKENS/BM), 256, GSMEM>>>(h1, w2, fc2_b, out,
        CC, HIDDEN, 2, x2, nullptr, nullptr, nullptr);
}

// round 10
// speedup vs baseline: 4.9511x; 1.0629x over previous
#include <cuda_runtime.h>
#include <cuda_fp16.h>
#include <math.h>
#include <stdint.h>

// ---------------- problem constants ----------------
#define BATCH 2
#define TT 8
#define HH 128
#define WWD 128
#define CC 192
#define TOKENS (BATCH*TT*HH*WWD)         // 262144
#define NWIN 2048
#define NWTOK 128
#define HEADS 6
#define HDIM 32
#define HIDDEN 768
#define QKVDIM 576
#define ATTSCALE 0.17677669529663687f

// ---------------- scratch ----------------
__device__ __half g_xw[(size_t)TOKENS * CC];
__device__ __half g_qkv[(size_t)NWIN * NWTOK * QKVDIM];
__device__ __half g_attnout[(size_t)TOKENS * CC];
__device__ float  g_x2[(size_t)TOKENS * CC];
__device__ __half g_h1[(size_t)TOKENS * HIDDEN];
__device__ __half g_wq[QKVDIM * CC];
__device__ __half g_wp[CC * CC];
__device__ __half g_w1[HIDDEN * CC];
__device__ __half g_w2[CC * HIDDEN];
__device__ float  g_biasf[HEADS * NWTOK * NWTOK];

// ---------------- helpers ----------------
__device__ __forceinline__ void cp_async16(uint32_t dst, const void* src) {
    asm volatile("cp.async.cg.shared.global [%0], [%1], 16;" :: "r"(dst), "l"(src));
}
__device__ __forceinline__ void cp_commit() { asm volatile("cp.async.commit_group;"); }
__device__ __forceinline__ void cp_wait1()  { asm volatile("cp.async.wait_group 1;"); }
__device__ __forceinline__ uint32_t smem_u32(const void* p) {
    uint32_t a;
    asm("{ .reg .u64 t; cvta.to.shared.u64 t, %1; cvt.u32.u64 %0, t; }" : "=r"(a) : "l"(p));
    return a;
}
__device__ __forceinline__ void mma_f16(float c[4], const uint32_t a[4], const uint32_t b[2]) {
    asm volatile(
        "mma.sync.aligned.m16n8k16.row.col.f32.f16.f16.f32 "
        "{%0,%1,%2,%3}, {%4,%5,%6,%7}, {%8,%9}, {%0,%1,%2,%3};"
        : "+f"(c[0]), "+f"(c[1]), "+f"(c[2]), "+f"(c[3])
        : "r"(a[0]), "r"(a[1]), "r"(a[2]), "r"(a[3]), "r"(b[0]), "r"(b[1]));
}
__device__ __forceinline__ void ldsm_x4(uint32_t r[4], uint32_t addr) {
    asm volatile("ldmatrix.sync.aligned.m8n8.x4.shared.b16 {%0,%1,%2,%3}, [%4];"
        : "=r"(r[0]), "=r"(r[1]), "=r"(r[2]), "=r"(r[3]) : "r"(addr));
}
__device__ __forceinline__ float gelu_exact(float x) {
    return 0.5f * x * (1.0f + erff(x * 0.70710678118654752f));
}

// ---------------- LayerNorm -> half (window scatter) ------------------------
__global__ void ln_kernel(const float* __restrict__ in,
                          const float* __restrict__ g,
                          const float* __restrict__ b,
                          __half* __restrict__ out, int windowed)
{
    int token = (blockIdx.x << 3) + (threadIdx.x >> 5);
    int lane  = threadIdx.x & 31;
    size_t base = (size_t)token * CC;

    float v[6]; float s = 0.f;
    #pragma unroll
    for (int j = 0; j < 6; ++j) { v[j] = in[base + lane + 32*j]; s += v[j]; }
    #pragma unroll
    for (int o = 16; o; o >>= 1) s += __shfl_xor_sync(0xffffffffu, s, o);
    float mu = s * (1.0f/192.0f);
    float vs = 0.f;
    #pragma unroll
    for (int j = 0; j < 6; ++j) { float d = v[j]-mu; vs += d*d; }
    #pragma unroll
    for (int o = 16; o; o >>= 1) vs += __shfl_xor_sync(0xffffffffu, vs, o);
    float rinv = rsqrtf(vs * (1.0f/192.0f) + 1e-5f);

    size_t obase;
    if (windowed) {
        int w = token & 127, h = (token >> 7) & 127, t = (token >> 14) & 7, bb = token >> 17;
        int win = ((bb*4 + (t >> 1))*16 + (h >> 3))*16 + (w >> 3);
        int n   = ((t & 1) << 6) | ((h & 7) << 3) | (w & 7);
        obase = ((size_t)win * NWTOK + n) * CC;
    } else obase = base;
    #pragma unroll
    for (int j = 0; j < 6; ++j) {
        int c = lane + 32*j;
        out[obase + c] = __float2half_rn((v[j]-mu)*rinv*g[c] + b[c]);
    }
}

// ---------------- merged setup: weight conversions + bias expansion --------
#define NWQ (QKVDIM*CC)
#define NWP (CC*CC)
#define NW1 (HIDDEN*CC)
#define NW2 (CC*HIDDEN)
#define NBF (HEADS*NWTOK*NWTOK)
#define NSETUP (NWQ+NWP+NW1+NW2+NBF)

__global__ void setup_kernel(const float* __restrict__ qkv_w, const float* __restrict__ proj_w,
                             const float* __restrict__ fc1_w, const float* __restrict__ fc2_w,
                             const float* __restrict__ bt,
                             __half* __restrict__ wq, __half* __restrict__ wp,
                             __half* __restrict__ w1, __half* __restrict__ w2,
                             float* __restrict__ bf)
{
    int i = blockIdx.x * 256 + threadIdx.x;
    if (i < NWQ) { wq[i] = __float2half_rn(qkv_w[i]); return; }
    i -= NWQ;
    if (i < NWP) { wp[i] = __float2half_rn(proj_w[i]); return; }
    i -= NWP;
    if (i < NW1) { w1[i] = __float2half_rn(fc1_w[i]); return; }
    i -= NW1;
    if (i < NW2) { w2[i] = __float2half_rn(fc2_w[i]); return; }
    i -= NW2;
    if (i < NBF) {
        int h = i >> 14, rem = i & 16383, n = rem >> 7, m = rem & 127;
        int t1 = n >> 6, h1 = (n >> 3) & 7, w1i = n & 7;
        int t2 = m >> 6, h2 = (m >> 3) & 7, w2i = m & 7;
        int bi = (t1 - t2 + 1)*225 + (h1 - h2 + 7)*15 + (w1i - w2i + 7);
        bf[i] = bt[bi*HEADS + h];
    }
}

// ---------------- fp16 mma GEMM: out[M,N]=A[M,K]@W[N,K]^T + bias -----------
// modes: 0 plain->half  1 GELU->half  2 +resid->f32
//        3 +win-reverse +resid->f32 x2  AND fused LN2 -> half xw
#define BM 128
#define BN 192
#define BK 64                               // halves per K chunk
#define PADH 72                             // halves per smem row (144B)
#define STG_HALVES ((BM + BN) * PADH)       // 23040
#define GSMEM (2*STG_HALVES*2)              // 92160 bytes

__device__ __forceinline__ void load_tiles(const __half* __restrict__ A, const __half* __restrict__ W,
                                           int K, int row0, int col0, int kt,
                                           __half* sA, __half* sB, int tid)
{
    uint32_t aA = smem_u32(sA), aB = smem_u32(sB);
    #pragma unroll
    for (int j = 0; j < 4; ++j) {            // A: 128 rows x 8 x 16B
        int idx = tid + j*256;
        int r = idx >> 3, c8 = idx & 7;
        cp_async16(aA + (uint32_t)(r*PADH + c8*8)*2, A + (size_t)(row0 + r)*K + kt + c8*8);
    }
    #pragma unroll
    for (int j = 0; j < 6; ++j) {            // B: 192 rows x 8 x 16B
        int idx = tid + j*256;
        int r = idx >> 3, c8 = idx & 7;
        cp_async16(aB + (uint32_t)(r*PADH + c8*8)*2, W + (size_t)(col0 + r)*K + kt + c8*8);
    }
}

__global__ __launch_bounds__(256, 1)
void gemm_mma(const __half* __restrict__ A, const __half* __restrict__ W,
              const float* __restrict__ bias, void* __restrict__ outv,
              int N, int K, int mode, const float* __restrict__ resid,
              const float* __restrict__ g2, const float* __restrict__ b2,
              __half* __restrict__ xw_out)
{
    extern __shared__ __half smh[];
    __half* sA[2] = { smh, smh + STG_HALVES };

    int tid = threadIdx.x;
    int lane = tid & 31, wid = tid >> 5;
    int warp_m = wid & 1, warp_n = wid >> 1;       // 2 x 4 warps, warp tile 64x48
    int col0 = blockIdx.x * BN;                    // col = x for L2 A-reuse
    int row0 = blockIdx.y * BM;
    int NC = K / BK;

    float acc[4][6][4];
    #pragma unroll
    for (int i = 0; i < 4; ++i)
        #pragma unroll
        for (int j = 0; j < 6; ++j)
            #pragma unroll
            for (int k = 0; k < 4; ++k) acc[i][j][k] = 0.f;

    int r0 = lane >> 2, c0 = lane & 3;

    // ldmatrix per-lane offsets (bytes within stage)
    int arow  = (lane & 7) + 8*((lane >> 3) & 1);
    int akoff = (lane >> 4) * 8;
    uint32_t aoff[4];
    #pragma unroll
    for (int mf = 0; mf < 4; ++mf)
        aoff[mf] = (uint32_t)(((warp_m*64 + mf*16 + arow)*PADH + akoff) * 2);
    int bmat   = lane >> 3;
    int brow   = lane & 7;
    int bnhalf = bmat >> 1;
    int bkoff  = (bmat & 1) * 8;
    uint32_t boff[3];
    #pragma unroll
    for (int j = 0; j < 3; ++j)
        boff[j] = (uint32_t)(BM*PADH*2 +
                  ((warp_n*48 + (2*j + bnhalf)*8 + brow)*PADH + bkoff) * 2);

    load_tiles(A, W, K, row0, col0, 0, sA[0], sA[0] + BM*PADH, tid);
    cp_commit();

    for (int i = 0; i < NC; ++i) {
        __syncthreads();
        if (i + 1 < NC)
            load_tiles(A, W, K, row0, col0, (i+1)*BK,
                       sA[(i+1)&1], sA[(i+1)&1] + BM*PADH, tid);
        cp_commit();
        cp_wait1();
        __syncthreads();

        uint32_t base = smem_u32(sA[i & 1]);

        #pragma unroll
        for (int kk = 0; kk < 4; ++kk) {
            uint32_t kb = kk*16*2;
            uint32_t af[4][4], bf[6][2];
            #pragma unroll
            for (int mf = 0; mf < 4; ++mf)
                ldsm_x4(af[mf], base + aoff[mf] + kb);
            #pragma unroll
            for (int j = 0; j < 3; ++j) {
                uint32_t br[4];
                ldsm_x4(br, base + boff[j] + kb);
                bf[2*j  ][0] = br[0]; bf[2*j  ][1] = br[1];
                bf[2*j+1][0] = br[2]; bf[2*j+1][1] = br[3];
            }
            #pragma unroll
            for (int mf = 0; mf < 4; ++mf)
                #pragma unroll
                for (int nf = 0; nf < 6; ++nf)
                    mma_f16(acc[mf][nf], af[mf], bf[nf]);
        }
    }

    // ---------------- epilogue ----------------
    if (mode != 3) {
        #pragma unroll
        for (int mf = 0; mf < 4; ++mf) {
            #pragma unroll
            for (int half = 0; half < 2; ++half) {
                int gm = row0 + warp_m*64 + mf*16 + half*8 + r0;
                size_t rowbase = (size_t)gm * N;
                #pragma unroll
                for (int nf = 0; nf < 6; ++nf) {
                    int gn = col0 + warp_n*48 + nf*8 + c0*2;
                    float v0 = acc[mf][nf][half*2 + 0] + bias[gn];
                    float v1 = acc[mf][nf][half*2 + 1] + bias[gn + 1];
                    if (mode == 0) {
                        *(__half2*)((__half*)outv + rowbase + gn) = __floats2half2_rn(v0, v1);
                    } else if (mode == 1) {
                        *(__half2*)((__half*)outv + rowbase + gn) =
                            __floats2half2_rn(gelu_exact(v0), gelu_exact(v1));
                    } else {
                        const float2 rr = *(const float2*)(resid + rowbase + gn);
                        float2 o; o.x = v0 + rr.x; o.y = v1 + rr.y;
                        *(float2*)((float*)outv + rowbase + gn) = o;
                    }
                }
            }
        }
        return;
    }

    // ---- mode 3: x2 = attn_proj + bias + shortcut, THEN fused LN2 -> xw ----
    __syncthreads();                      // mainloop smem dead; reuse for reductions
    float* redsum = (float*)smh;          // [128]
    float* redsq  = (float*)smh + 128;    // [128]
    if (tid < 128) { redsum[tid] = 0.f; redsq[tid] = 0.f; }
    __syncthreads();

    int toks[4][2];
    #pragma unroll
    for (int mf = 0; mf < 4; ++mf) {
        #pragma unroll
        for (int half = 0; half < 2; ++half) {
            int gm = row0 + warp_m*64 + mf*16 + half*8 + r0;
            int win = gm >> 7, n = gm & 127;
            int bb = win >> 10, rem = win & 1023;
            int t = (rem >> 8)*2 + (n >> 6);
            int h = ((rem >> 4) & 15)*8 + ((n >> 3) & 7);
            int w = (rem & 15)*8 + (n & 7);
            int token = ((bb*TT + t)*HH + h)*WWD + w;
            toks[mf][half] = token;
            size_t rowbase = (size_t)token * CC;

            float psum = 0.f, psq = 0.f;
            #pragma unroll
            for (int nf = 0; nf < 6; ++nf) {
                int gn = col0 + warp_n*48 + nf*8 + c0*2;
                const float2 rr = *(const float2*)(resid + rowbase + gn);
                float v0 = acc[mf][nf][half*2+0] + bias[gn]   + rr.x;
                float v1 = acc[mf][nf][half*2+1] + bias[gn+1] + rr.y;
                acc[mf][nf][half*2+0] = v0;
                acc[mf][nf][half*2+1] = v1;
                float2 o; o.x = v0; o.y = v1;
                *(float2*)((float*)outv + rowbase + gn) = o;
                psum += v0 + v1;
                psq  += v0*v0 + v1*v1;
            }
            psum += __shfl_xor_sync(0xffffffffu, psum, 1);
            psum += __shfl_xor_sync(0xffffffffu, psum, 2);
            psq  += __shfl_xor_sync(0xffffffffu, psq, 1);
            psq  += __shfl_xor_sync(0xffffffffu, psq, 2);
            if (c0 == 0) {
                int lr = warp_m*64 + mf*16 + half*8 + r0;
                atomicAdd(&redsum[lr], psum);
                atomicAdd(&redsq[lr],  psq);
            }
        }
    }
    __syncthreads();

    #pragma unroll
    for (int mf = 0; mf < 4; ++mf) {
        #pragma unroll
        for (int half = 0; half < 2; ++half) {
            int lr = warp_m*64 + mf*16 + half*8 + r0;
            float mu  = redsum[lr] * (1.0f/192.0f);
            float var = redsq[lr] * (1.0f/192.0f) - mu*mu;
            float rinv = rsqrtf(var + 1e-5f);
            size_t rowbase = (size_t)toks[mf][half] * CC;
            #pragma unroll
            for (int nf = 0; nf < 6; ++nf) {
                int gn = col0 + warp_n*48 + nf*8 + c0*2;
                float n0 = (acc[mf][nf][half*2+0] - mu)*rinv*g2[gn]   + b2[gn];
                float n1 = (acc[mf][nf][half*2+1] - mu)*rinv*g2[gn+1] + b2[gn+1];
                *(__half2*)(xw_out + rowbase + gn) = __floats2half2_rn(n0, n1);
            }
        }
    }
}

// ---------------- attention via fp16 mma + ldmatrix -------------------------
// one block per (head, window); 8 warps x 16 rows.
// halves: Ps 128x136 (overlays Qs 128x40 + Ks 128x40), Vts 32x136
#define PQH 40
#define PPH 136
#define ATT_SMEM ((128*PPH + 32*PPH)*2)     // 43520 bytes

__global__ __launch_bounds__(256, 2)
void attn_mma(const __half* __restrict__ qkv,
              const float* __restrict__ biasf,
              __half* __restrict__ outp)
{
    extern __shared__ __half sh[];
    __half* Ps  = sh;
    __half* Qs  = sh;
    __half* Ks  = sh + 128*PQH;
    __half* Vts = sh + 128*PPH;

    int head = blockIdx.x, win = blockIdx.y;
    int tid = threadIdx.x, lane = tid & 31, w = tid >> 5;   // 8 warps
    int r0 = lane >> 2, c0 = lane & 3;

    // ---- stage: threads 0-127 copy Q,K rows; threads 128-255 build V^T ----
    if (tid < 128) {
        const __half* rb = qkv + (size_t)win*NWTOK*QKVDIM + (size_t)tid*QKVDIM + head*HDIM;
        const uint4* q4 = (const uint4*)(rb);
        const uint4* k4 = (const uint4*)(rb + CC);
        uint4* qd = (uint4*)(Qs + tid*PQH);
        uint4* kd = (uint4*)(Ks + tid*PQH);
        qd[0] = q4[0]; qd[1] = q4[1]; qd[2] = q4[2]; qd[3] = q4[3];
        kd[0] = k4[0]; kd[1] = k4[1]; kd[2] = k4[2]; kd[3] = k4[3];
    } else {
        int tok = tid - 128;
        const uint4* v4 = (const uint4*)(qkv + (size_t)win*NWTOK*QKVDIM +
                                         (size_t)tok*QKVDIM + 2*CC + head*HDIM);
        #pragma unroll
        for (int q = 0; q < 4; ++q) {
            uint4 vv = v4[q];
            const __half* vh = (const __half*)&vv;
            #pragma unroll
            for (int d = 0; d < 8; ++d) Vts[(q*8 + d)*PPH + tok] = vh[d];
        }
    }
    __syncthreads();

    // ldmatrix lane-address components
    int arow  = (lane & 7) + 8*((lane >> 3) & 1);
    int akoff = (lane >> 4) * 8;
    int bmat  = lane >> 3, brow = lane & 7;
    int bnhalf = bmat >> 1, bkoff = (bmat & 1) * 8;
    uint32_t base = smem_u32(sh);

    // ---- S = Q K^T : warp w rows [16w, 16w+16) ----
    float s[16][4];
    #pragma unroll
    for (int b = 0; b < 16; ++b)
        #pragma unroll
        for (int c = 0; c < 4; ++c) s[b][c] = 0.f;

    {
        uint32_t aoffQ = (uint32_t)(((w*16 + arow)*PQH + akoff) * 2);
        #pragma unroll
        for (int kk = 0; kk < 2; ++kk) {
            uint32_t kb = kk*32;
            uint32_t af[4];
            ldsm_x4(af, base + aoffQ + kb);
            #pragma unroll
            for (int j = 0; j < 8; ++j) {
                uint32_t br[4];
                uint32_t bo = (uint32_t)(128*PQH*2 +
                              (((2*j + bnhalf)*8 + brow)*PQH + bkoff) * 2);
                ldsm_x4(br, base + bo + kb);
                uint32_t b0[2] = { br[0], br[1] };
                uint32_t b1[2] = { br[2], br[3] };
                mma_f16(s[2*j  ], af, b0);
                mma_f16(s[2*j+1], af, b1);
            }
        }
    }

    // ---- scale + bias + row softmax (normalization deferred) ----
    float inv[2];
    const float* bh = biasf + (size_t)head*NWTOK*NWTOK;
    #pragma unroll
    for (int half = 0; half < 2; ++half) {
        int r = w*16 + half*8 + r0;
        const float2* brw = (const float2*)(bh + r*NWTOK) + c0;
        float mx = -1e30f;
        #pragma unroll
        for (int nf = 0; nf < 16; ++nf) {
            float2 bb = brw[nf*4];
            float v0 = s[nf][half*2+0]*ATTSCALE + bb.x;
            float v1 = s[nf][half*2+1]*ATTSCALE + bb.y;
            s[nf][half*2+0] = v0;
            s[nf][half*2+1] = v1;
            mx = fmaxf(mx, fmaxf(v0, v1));
        }
        mx = fmaxf(mx, __shfl_xor_sync(0xffffffffu, mx, 1));
        mx = fmaxf(mx, __shfl_xor_sync(0xffffffffu, mx, 2));
        float sum = 0.f;
        #pragma unroll
        for (int nf = 0; nf < 16; ++nf) {
            float e0 = __expf(s[nf][half*2+0] - mx);
            float e1 = __expf(s[nf][half*2+1] - mx);
            s[nf][half*2+0] = e0;
            s[nf][half*2+1] = e1;
            sum += e0 + e1;
        }
        sum += __shfl_xor_sync(0xffffffffu, sum, 1);
        sum += __shfl_xor_sync(0xffffffffu, sum, 2);
        inv[half] = 1.0f / sum;
    }

    __syncthreads();   // all warps done reading Qs/Ks before P overwrites

    // ---- store P (half) ----
    #pragma unroll
    for (int half = 0; half < 2; ++half) {
        int r = w*16 + half*8 + r0;
        __half* pr = Ps + r*PPH + 2*c0;
        #pragma unroll
        for (int nf = 0; nf < 16; ++nf)
            *(__half2*)(pr + nf*8) =
                __floats2half2_rn(s[nf][half*2+0], s[nf][half*2+1]);
    }
    __syncthreads();

    // ---- O = P V ----
    float o[4][4];
    #pragma unroll
    for (int b = 0; b < 4; ++b)
        #pragma unroll
        for (int c = 0; c < 4; ++c) o[b][c] = 0.f;

    {
        uint32_t aoffP = (uint32_t)(((w*16 + arow)*PPH + akoff) * 2);
        #pragma unroll
        for (int kk = 0; kk < 8; ++kk) {
            uint32_t kb = kk*32;
            uint32_t af[4];
            ldsm_x4(af, base + aoffP + kb);
            #pragma unroll
            for (int j = 0; j < 2; ++j) {
                uint32_t br[4];
                uint32_t bo = (uint32_t)(128*PPH*2 +
                              (((2*j + bnhalf)*8 + brow)*PPH + bkoff) * 2);
                ldsm_x4(br, base + bo + kb);
                uint32_t b0[2] = { br[0], br[1] };
                uint32_t b1[2] = { br[2], br[3] };
                mma_f16(o[2*j  ], af, b0);
                mma_f16(o[2*j+1], af, b1);
            }
        }
    }

    // ---- epilogue: normalize + store half ----
    #pragma unroll
    for (int half = 0; half < 2; ++half) {
        int r = w*16 + half*8 + r0;
        float sc = inv[half];
        __half* op = outp + ((size_t)win*NWTOK + r)*CC + head*HDIM;
        #pragma unroll
        for (int nf = 0; nf < 4; ++nf)
            *(__half2*)(op + nf*8 + 2*c0) =
                __floats2half2_rn(o[nf][half*2+0]*sc, o[nf][half*2+1]*sc);
    }
}

// ---------------- launch ----------------
extern "C" void kernel_launch(void* const* d_in, const int* in_sizes, int n_in,
                              void* d_out, int out_size)
{
    const float* x        = (const float*)d_in[0];
    const float* norm1_g  = (const float*)d_in[1];
    const float* norm1_b  = (const float*)d_in[2];
    const float* qkv_w    = (const float*)d_in[3];
    const float* qkv_b    = (const float*)d_in[4];
    const float* bias_tab = (const float*)d_in[5];
    const float* proj_w   = (const float*)d_in[6];
    const float* proj_b   = (const float*)d_in[7];
    const float* norm2_g  = (const float*)d_in[8];
    const float* norm2_b  = (const float*)d_in[9];
    const float* fc1_w    = (const float*)d_in[10];
    const float* fc1_b    = (const float*)d_in[11];
    const float* fc2_w    = (const float*)d_in[12];
    const float* fc2_b    = (const float*)d_in[13];
    float* out = (float*)d_out;

    __half *xw, *qkvb, *attno, *h1, *wq, *wp, *w1, *w2;
    float *x2, *bf;
    cudaGetSymbolAddress((void**)&xw,    g_xw);
    cudaGetSymbolAddress((void**)&qkvb,  g_qkv);
    cudaGetSymbolAddress((void**)&attno, g_attnout);
    cudaGetSymbolAddress((void**)&x2,    g_x2);
    cudaGetSymbolAddress((void**)&h1,    g_h1);
    cudaGetSymbolAddress((void**)&wq,    g_wq);
    cudaGetSymbolAddress((void**)&wp,    g_wp);
    cudaGetSymbolAddress((void**)&w1,    g_w1);
    cudaGetSymbolAddress((void**)&w2,    g_w2);
    cudaGetSymbolAddress((void**)&bf,    g_biasf);

    cudaFuncSetAttribute(attn_mma, cudaFuncAttributeMaxDynamicSharedMemorySize, ATT_SMEM);
    cudaFuncSetAttribute(gemm_mma, cudaFuncAttributeMaxDynamicSharedMemorySize, GSMEM);

    // merged setup
    setup_kernel<<<(NSETUP+255)/256, 256>>>(qkv_w, proj_w, fc1_w, fc2_w, bias_tab,
                                            wq, wp, w1, w2, bf);

    // 1. LN1 + window partition -> half
    ln_kernel<<<TOKENS/8, 256>>>(x, norm1_g, norm1_b, xw, 1);
    // 2. QKV GEMM -> half
    gemm_mma<<<dim3(QKVDIM/BN, TOKENS/BM), 256, GSMEM>>>(xw, wq, qkv_b, qkvb,
        QKVDIM, CC, 0, nullptr, nullptr, nullptr, nullptr);
    // 3. windowed attention -> half
    attn_mma<<<dim3(HEADS, NWIN), 256, ATT_SMEM>>>(qkvb, bf, attno);
    // 4. proj + window-reverse + residual -> x2 (f32), fused LN2 -> xw (half)
    gemm_mma<<<dim3(CC/BN, TOKENS/BM), 256, GSMEM>>>(attno, wp, proj_b, x2,
        CC, CC, 3, x, norm2_g, norm2_b, xw);
    // 5. FC1 + GELU -> half
    gemm_mma<<<dim3(HIDDEN/BN, TOKENS/BM), 256, GSMEM>>>(xw, w1, fc1_b, h1,
        HIDDEN, CC, 1, nullptr, nullptr, nullptr, nullptr);
    // 6. FC2 + residual -> out (f32)
    gemm_mma<<<dim3(CC/BN, TOKENS/BM), 256, GSMEM>>>(h1, w2, fc2_b, out,
        CC, HIDDEN, 2, x2, nullptr, nullptr, nullptr);
}

// round 11
// speedup vs baseline: 5.2024x; 1.0508x over previous
#include <cuda_runtime.h>
#include <cuda_fp16.h>
#include <math.h>
#include <stdint.h>

// ---------------- problem constants ----------------
#define BATCH 2
#define TT 8
#define HH 128
#define WWD 128
#define CC 192
#define TOKENS (BATCH*TT*HH*WWD)         // 262144
#define NWIN 2048
#define NWTOK 128
#define HEADS 6
#define HDIM 32
#define HIDDEN 768
#define QKVDIM 576
#define ATTSCALE 0.17677669529663687f

// ---------------- scratch ----------------
__device__ __half g_xw[(size_t)TOKENS * CC];
__device__ __half g_qkv[(size_t)NWIN * NWTOK * QKVDIM];
__device__ __half g_attnout[(size_t)TOKENS * CC];
__device__ float  g_x2[(size_t)TOKENS * CC];
__device__ __half g_h1[(size_t)TOKENS * HIDDEN];
__device__ __half g_wq[QKVDIM * CC];
__device__ __half g_wp[CC * CC];
__device__ __half g_w1[HIDDEN * CC];
__device__ __half g_w2[CC * HIDDEN];
__device__ float  g_biasf[HEADS * NWTOK * NWTOK];

// ---------------- helpers ----------------
__device__ __forceinline__ void cp_async16(uint32_t dst, const void* src) {
    asm volatile("cp.async.cg.shared.global [%0], [%1], 16;" :: "r"(dst), "l"(src));
}
__device__ __forceinline__ void cp_commit() { asm volatile("cp.async.commit_group;"); }
__device__ __forceinline__ void cp_wait1()  { asm volatile("cp.async.wait_group 1;"); }
__device__ __forceinline__ uint32_t smem_u32(const void* p) {
    uint32_t a;
    asm("{ .reg .u64 t; cvta.to.shared.u64 t, %1; cvt.u32.u64 %0, t; }" : "=r"(a) : "l"(p));
    return a;
}
__device__ __forceinline__ void mma_f16(float c[4], const uint32_t a[4], const uint32_t b[2]) {
    asm volatile(
        "mma.sync.aligned.m16n8k16.row.col.f32.f16.f16.f32 "
        "{%0,%1,%2,%3}, {%4,%5,%6,%7}, {%8,%9}, {%0,%1,%2,%3};"
        : "+f"(c[0]), "+f"(c[1]), "+f"(c[2]), "+f"(c[3])
        : "r"(a[0]), "r"(a[1]), "r"(a[2]), "r"(a[3]), "r"(b[0]), "r"(b[1]));
}
__device__ __forceinline__ void ldsm_x4(uint32_t r[4], uint32_t addr) {
    asm volatile("ldmatrix.sync.aligned.m8n8.x4.shared.b16 {%0,%1,%2,%3}, [%4];"
        : "=r"(r[0]), "=r"(r[1]), "=r"(r[2]), "=r"(r[3]) : "r"(addr));
}
__device__ __forceinline__ float gelu_exact(float x) {
    return 0.5f * x * (1.0f + erff(x * 0.70710678118654752f));
}

// ---------------- LayerNorm -> half (window scatter) ------------------------
__global__ void ln_kernel(const float* __restrict__ in,
                          const float* __restrict__ g,
                          const float* __restrict__ b,
                          __half* __restrict__ out, int windowed)
{
    int token = (blockIdx.x << 3) + (threadIdx.x >> 5);
    int lane  = threadIdx.x & 31;
    size_t base = (size_t)token * CC;

    float v[6]; float s = 0.f;
    #pragma unroll
    for (int j = 0; j < 6; ++j) { v[j] = in[base + lane + 32*j]; s += v[j]; }
    #pragma unroll
    for (int o = 16; o; o >>= 1) s += __shfl_xor_sync(0xffffffffu, s, o);
    float mu = s * (1.0f/192.0f);
    float vs = 0.f;
    #pragma unroll
    for (int j = 0; j < 6; ++j) { float d = v[j]-mu; vs += d*d; }
    #pragma unroll
    for (int o = 16; o; o >>= 1) vs += __shfl_xor_sync(0xffffffffu, vs, o);
    float rinv = rsqrtf(vs * (1.0f/192.0f) + 1e-5f);

    size_t obase;
    if (windowed) {
        int w = token & 127, h = (token >> 7) & 127, t = (token >> 14) & 7, bb = token >> 17;
        int win = ((bb*4 + (t >> 1))*16 + (h >> 3))*16 + (w >> 3);
        int n   = ((t & 1) << 6) | ((h & 7) << 3) | (w & 7);
        obase = ((size_t)win * NWTOK + n) * CC;
    } else obase = base;
    #pragma unroll
    for (int j = 0; j < 6; ++j) {
        int c = lane + 32*j;
        out[obase + c] = __float2half_rn((v[j]-mu)*rinv*g[c] + b[c]);
    }
}

// ---------------- merged setup ----------------
#define NWQ (QKVDIM*CC)
#define NWP (CC*CC)
#define NW1 (HIDDEN*CC)
#define NW2 (CC*HIDDEN)
#define NBF (HEADS*NWTOK*NWTOK)
#define NSETUP (NWQ+NWP+NW1+NW2+NBF)

__global__ void setup_kernel(const float* __restrict__ qkv_w, const float* __restrict__ proj_w,
                             const float* __restrict__ fc1_w, const float* __restrict__ fc2_w,
                             const float* __restrict__ bt,
                             __half* __restrict__ wq, __half* __restrict__ wp,
                             __half* __restrict__ w1, __half* __restrict__ w2,
                             float* __restrict__ bf)
{
    int i = blockIdx.x * 256 + threadIdx.x;
    if (i < NWQ) { wq[i] = __float2half_rn(qkv_w[i]); return; }
    i -= NWQ;
    if (i < NWP) { wp[i] = __float2half_rn(proj_w[i]); return; }
    i -= NWP;
    if (i < NW1) { w1[i] = __float2half_rn(fc1_w[i]); return; }
    i -= NW1;
    if (i < NW2) { w2[i] = __float2half_rn(fc2_w[i]); return; }
    i -= NW2;
    if (i < NBF) {
        int h = i >> 14, rem = i & 16383, n = rem >> 7, m = rem & 127;
        int t1 = n >> 6, h1 = (n >> 3) & 7, w1i = n & 7;
        int t2 = m >> 6, h2 = (m >> 3) & 7, w2i = m & 7;
        int bi = (t1 - t2 + 1)*225 + (h1 - h2 + 7)*15 + (w1i - w2i + 7);
        bf[i] = bt[bi*HEADS + h];
    }
}

// ---------------- templated fp16 mma GEMM ----------------------------------
// out[M,N]=A[M,K]@W[N,K]^T + bias
// BN_: block N tile; WMG: warps along M; MF: 16-row frags per warp; NF fixed 6
// modes: 0 plain->half  1 GELU->half  2 +resid->f32
//        3 +win-reverse +resid->f32 AND fused LN2 -> half xw  (BN_=192 only)
#define BM 128
#define BK 64
#define PADH 72

template<int BN_, int WMG, int MF, int MINB>
__global__ __launch_bounds__(256, MINB)
void gemm_t(const __half* __restrict__ A, const __half* __restrict__ W,
            const float* __restrict__ bias, void* __restrict__ outv,
            int N, int K, int mode, const float* __restrict__ resid,
            const float* __restrict__ g2, const float* __restrict__ b2,
            __half* __restrict__ xw_out)
{
    constexpr int NF = 6;
    constexpr int STG_HALVES = (BM + BN_) * PADH;
    extern __shared__ __half smh[];
    __half* sA[2] = { smh, smh + STG_HALVES };

    int tid = threadIdx.x;
    int lane = tid & 31, wid = tid >> 5;
    int warp_m = wid % WMG, warp_n = wid / WMG;
    int col0 = blockIdx.x * BN_;
    int row0 = blockIdx.y * BM;
    int NC = K / BK;

    float acc[MF][NF][4];
    #pragma unroll
    for (int i = 0; i < MF; ++i)
        #pragma unroll
        for (int j = 0; j < NF; ++j)
            #pragma unroll
            for (int k = 0; k < 4; ++k) acc[i][j][k] = 0.f;

    int r0 = lane >> 2, c0 = lane & 3;

    int arow  = (lane & 7) + 8*((lane >> 3) & 1);
    int akoff = (lane >> 4) * 8;
    uint32_t aoff[MF];
    #pragma unroll
    for (int mf = 0; mf < MF; ++mf)
        aoff[mf] = (uint32_t)(((warp_m*(MF*16) + mf*16 + arow)*PADH + akoff) * 2);
    int bmat   = lane >> 3;
    int brow   = lane & 7;
    int bnhalf = bmat >> 1;
    int bkoff  = (bmat & 1) * 8;
    uint32_t boff[3];
    #pragma unroll
    for (int j = 0; j < 3; ++j)
        boff[j] = (uint32_t)(BM*PADH*2 +
                  ((warp_n*48 + (2*j + bnhalf)*8 + brow)*PADH + bkoff) * 2);

    // tile loader (A: 128 rows, B: BN_ rows; 8 x 16B per row)
    auto load_tiles = [&](int kt, __half* stage) {
        uint32_t aA = smem_u32(stage), aB = smem_u32(stage + BM*PADH);
        #pragma unroll
        for (int j = 0; j < 4; ++j) {
            int idx = tid + j*256;
            int r = idx >> 3, c8 = idx & 7;
            cp_async16(aA + (uint32_t)(r*PADH + c8*8)*2, A + (size_t)(row0 + r)*K + kt + c8*8);
        }
        #pragma unroll
        for (int j = 0; j < BN_/32; ++j) {
            int idx = tid + j*256;
            int r = idx >> 3, c8 = idx & 7;
            cp_async16(aB + (uint32_t)(r*PADH + c8*8)*2, W + (size_t)(col0 + r)*K + kt + c8*8);
        }
    };

    load_tiles(0, sA[0]);
    cp_commit();

    for (int i = 0; i < NC; ++i) {
        __syncthreads();
        if (i + 1 < NC)
            load_tiles((i+1)*BK, sA[(i+1)&1]);
        cp_commit();
        cp_wait1();
        __syncthreads();

        uint32_t base = smem_u32(sA[i & 1]);

        #pragma unroll
        for (int kk = 0; kk < 4; ++kk) {
            uint32_t kb = kk*16*2;
            uint32_t af[MF][4], bf[NF][2];
            #pragma unroll
            for (int mf = 0; mf < MF; ++mf)
                ldsm_x4(af[mf], base + aoff[mf] + kb);
            #pragma unroll
            for (int j = 0; j < 3; ++j) {
                uint32_t br[4];
                ldsm_x4(br, base + boff[j] + kb);
                bf[2*j  ][0] = br[0]; bf[2*j  ][1] = br[1];
                bf[2*j+1][0] = br[2]; bf[2*j+1][1] = br[3];
            }
            #pragma unroll
            for (int mf = 0; mf < MF; ++mf)
                #pragma unroll
                for (int nf = 0; nf < NF; ++nf)
                    mma_f16(acc[mf][nf], af[mf], bf[nf]);
        }
    }

    // ---------------- epilogue ----------------
    if (mode != 3) {
        #pragma unroll
        for (int mf = 0; mf < MF; ++mf) {
            #pragma unroll
            for (int half = 0; half < 2; ++half) {
                int gm = row0 + warp_m*(MF*16) + mf*16 + half*8 + r0;
                size_t rowbase = (size_t)gm * N;
                #pragma unroll
                for (int nf = 0; nf < NF; ++nf) {
                    int gn = col0 + warp_n*48 + nf*8 + c0*2;
                    float v0 = acc[mf][nf][half*2 + 0] + bias[gn];
                    float v1 = acc[mf][nf][half*2 + 1] + bias[gn + 1];
                    if (mode == 0) {
                        *(__half2*)((__half*)outv + rowbase + gn) = __floats2half2_rn(v0, v1);
                    } else if (mode == 1) {
                        *(__half2*)((__half*)outv + rowbase + gn) =
                            __floats2half2_rn(gelu_exact(v0), gelu_exact(v1));
                    } else {
                        const float2 rr = *(const float2*)(resid + rowbase + gn);
                        float2 o; o.x = v0 + rr.x; o.y = v1 + rr.y;
                        *(float2*)((float*)outv + rowbase + gn) = o;
                    }
                }
            }
        }
        return;
    }

    // ---- mode 3 (BN_=192): x2 = proj + bias + shortcut, fused LN2 -> xw ----
    __syncthreads();
    float* redsum = (float*)smh;
    float* redsq  = (float*)smh + 128;
    if (tid < 128) { redsum[tid] = 0.f; redsq[tid] = 0.f; }
    __syncthreads();

    int toks[MF][2];
    #pragma unroll
    for (int mf = 0; mf < MF; ++mf) {
        #pragma unroll
        for (int half = 0; half < 2; ++half) {
            int gm = row0 + warp_m*(MF*16) + mf*16 + half*8 + r0;
            int win = gm >> 7, n = gm & 127;
            int bb = win >> 10, rem = win & 1023;
            int t = (rem >> 8)*2 + (n >> 6);
            int h = ((rem >> 4) & 15)*8 + ((n >> 3) & 7);
            int w = (rem & 15)*8 + (n & 7);
            int token = ((bb*TT + t)*HH + h)*WWD + w;
            toks[mf][half] = token;
            size_t rowbase = (size_t)token * CC;

            float psum = 0.f, psq = 0.f;
            #pragma unroll
            for (int nf = 0; nf < NF; ++nf) {
                int gn = col0 + warp_n*48 + nf*8 + c0*2;
                const float2 rr = *(const float2*)(resid + rowbase + gn);
                float v0 = acc[mf][nf][half*2+0] + bias[gn]   + rr.x;
                float v1 = acc[mf][nf][half*2+1] + bias[gn+1] + rr.y;
                acc[mf][nf][half*2+0] = v0;
                acc[mf][nf][half*2+1] = v1;
                float2 o; o.x = v0; o.y = v1;
                *(float2*)((float*)outv + rowbase + gn) = o;
                psum += v0 + v1;
                psq  += v0*v0 + v1*v1;
            }
            psum += __shfl_xor_sync(0xffffffffu, psum, 1);
            psum += __shfl_xor_sync(0xffffffffu, psum, 2);
            psq  += __shfl_xor_sync(0xffffffffu, psq, 1);
            psq  += __shfl_xor_sync(0xffffffffu, psq, 2);
            if (c0 == 0) {
                int lr = warp_m*(MF*16) + mf*16 + half*8 + r0;
                atomicAdd(&redsum[lr], psum);
                atomicAdd(&redsq[lr],  psq);
            }
        }
    }
    __syncthreads();

    #pragma unroll
    for (int mf = 0; mf < MF; ++mf) {
        #pragma unroll
        for (int half = 0; half < 2; ++half) {
            int lr = warp_m*(MF*16) + mf*16 + half*8 + r0;
            float mu  = redsum[lr] * (1.0f/192.0f);
            float var = redsq[lr] * (1.0f/192.0f) - mu*mu;
            float rinv = rsqrtf(var + 1e-5f);
            size_t rowbase = (size_t)toks[mf][half] * CC;
            #pragma unroll
            for (int nf = 0; nf < NF; ++nf) {
                int gn = col0 + warp_n*48 + nf*8 + c0*2;
                float n0 = (acc[mf][nf][half*2+0] - mu)*rinv*g2[gn]   + b2[gn];
                float n1 = (acc[mf][nf][half*2+1] - mu)*rinv*g2[gn+1] + b2[gn+1];
                *(__half2*)(xw_out + rowbase + gn) = __floats2half2_rn(n0, n1);
            }
        }
    }
}

#define GSMEM192 (2*(BM+192)*PADH*2)
#define GSMEM96  (2*(BM+96)*PADH*2)

// ---------------- attention via fp16 mma + ldmatrix -------------------------
#define PQH 40
#define PPH 136
#define ATT_SMEM ((128*PPH + 32*PPH)*2)     // 43520 bytes

__global__ __launch_bounds__(256, 2)
void attn_mma(const __half* __restrict__ qkv,
              const float* __restrict__ biasf,
              __half* __restrict__ outp)
{
    extern __shared__ __half sh[];
    __half* Ps  = sh;
    __half* Qs  = sh;
    __half* Ks  = sh + 128*PQH;
    __half* Vts = sh + 128*PPH;

    int head = blockIdx.x, win = blockIdx.y;
    int tid = threadIdx.x, lane = tid & 31, w = tid >> 5;
    int r0 = lane >> 2, c0 = lane & 3;

    if (tid < 128) {
        const __half* rb = qkv + (size_t)win*NWTOK*QKVDIM + (size_t)tid*QKVDIM + head*HDIM;
        const uint4* q4 = (const uint4*)(rb);
        const uint4* k4 = (const uint4*)(rb + CC);
        uint4* qd = (uint4*)(Qs + tid*PQH);
        uint4* kd = (uint4*)(Ks + tid*PQH);
        qd[0] = q4[0]; qd[1] = q4[1]; qd[2] = q4[2]; qd[3] = q4[3];
        kd[0] = k4[0]; kd[1] = k4[1]; kd[2] = k4[2]; kd[3] = k4[3];
    } else {
        int tok = tid - 128;
        const uint4* v4 = (const uint4*)(qkv + (size_t)win*NWTOK*QKVDIM +
                                         (size_t)tok*QKVDIM + 2*CC + head*HDIM);
        #pragma unroll
        for (int q = 0; q < 4; ++q) {
            uint4 vv = v4[q];
            const __half* vh = (const __half*)&vv;
            #pragma unroll
            for (int d = 0; d < 8; ++d) Vts[(q*8 + d)*PPH + tok] = vh[d];
        }
    }
    __syncthreads();

    int arow  = (lane & 7) + 8*((lane >> 3) & 1);
    int akoff = (lane >> 4) * 8;
    int bmat  = lane >> 3, brow = lane & 7;
    int bnhalf = bmat >> 1, bkoff = (bmat & 1) * 8;
    uint32_t base = smem_u32(sh);

    float s[16][4];
    #pragma unroll
    for (int b = 0; b < 16; ++b)
        #pragma unroll
        for (int c = 0; c < 4; ++c) s[b][c] = 0.f;

    {
        uint32_t aoffQ = (uint32_t)(((w*16 + arow)*PQH + akoff) * 2);
        #pragma unroll
        for (int kk = 0; kk < 2; ++kk) {
            uint32_t kb = kk*32;
            uint32_t af[4];
            ldsm_x4(af, base + aoffQ + kb);
            #pragma unroll
            for (int j = 0; j < 8; ++j) {
                uint32_t br[4];
                uint32_t bo = (uint32_t)(128*PQH*2 +
                              (((2*j + bnhalf)*8 + brow)*PQH + bkoff) * 2);
                ldsm_x4(br, base + bo + kb);
                uint32_t b0[2] = { br[0], br[1] };
                uint32_t b1[2] = { br[2], br[3] };
                mma_f16(s[2*j  ], af, b0);
                mma_f16(s[2*j+1], af, b1);
            }
        }
    }

    float inv[2];
    const float* bh = biasf + (size_t)head*NWTOK*NWTOK;
    #pragma unroll
    for (int half = 0; half < 2; ++half) {
        int r = w*16 + half*8 + r0;
        const float2* brw = (const float2*)(bh + r*NWTOK) + c0;
        float mx = -1e30f;
        #pragma unroll
        for (int nf = 0; nf < 16; ++nf) {
            float2 bb = brw[nf*4];
            float v0 = s[nf][half*2+0]*ATTSCALE + bb.x;
            float v1 = s[nf][half*2+1]*ATTSCALE + bb.y;
            s[nf][half*2+0] = v0;
            s[nf][half*2+1] = v1;
            mx = fmaxf(mx, fmaxf(v0, v1));
        }
        mx = fmaxf(mx, __shfl_xor_sync(0xffffffffu, mx, 1));
        mx = fmaxf(mx, __shfl_xor_sync(0xffffffffu, mx, 2));
        float sum = 0.f;
        #pragma unroll
        for (int nf = 0; nf < 16; ++nf) {
            float e0 = __expf(s[nf][half*2+0] - mx);
            float e1 = __expf(s[nf][half*2+1] - mx);
            s[nf][half*2+0] = e0;
            s[nf][half*2+1] = e1;
            sum += e0 + e1;
        }
        sum += __shfl_xor_sync(0xffffffffu, sum, 1);
        sum += __shfl_xor_sync(0xffffffffu, sum, 2);
        inv[half] = 1.0f / sum;
    }

    __syncthreads();

    #pragma unroll
    for (int half = 0; half < 2; ++half) {
        int r = w*16 + half*8 + r0;
        __half* pr = Ps + r*PPH + 2*c0;
        #pragma unroll
        for (int nf = 0; nf < 16; ++nf)
            *(__half2*)(pr + nf*8) =
                __floats2half2_rn(s[nf][half*2+0], s[nf][half*2+1]);
    }
    __syncthreads();

    float o[4][4];
    #pragma unroll
    for (int b = 0; b < 4; ++b)
        #pragma unroll
        for (int c = 0; c < 4; ++c) o[b][c] = 0.f;

    {
        uint32_t aoffP = (uint32_t)(((w*16 + arow)*PPH + akoff) * 2);
        #pragma unroll
        for (int kk = 0; kk < 8; ++kk) {
            uint32_t kb = kk*32;
            uint32_t af[4];
            ldsm_x4(af, base + aoffP + kb);
            #pragma unroll
            for (int j = 0; j < 2; ++j) {
                uint32_t br[4];
                uint32_t bo = (uint32_t)(128*PPH*2 +
                              (((2*j + bnhalf)*8 + brow)*PPH + bkoff) * 2);
                ldsm_x4(br, base + bo + kb);
                uint32_t b0[2] = { br[0], br[1] };
                uint32_t b1[2] = { br[2], br[3] };
                mma_f16(o[2*j  ], af, b0);
                mma_f16(o[2*j+1], af, b1);
            }
        }
    }

    #pragma unroll
    for (int half = 0; half < 2; ++half) {
        int r = w*16 + half*8 + r0;
        float sc = inv[half];
        __half* op = outp + ((size_t)win*NWTOK + r)*CC + head*HDIM;
        #pragma unroll
        for (int nf = 0; nf < 4; ++nf)
            *(__half2*)(op + nf*8 + 2*c0) =
                __floats2half2_rn(o[nf][half*2+0]*sc, o[nf][half*2+1]*sc);
    }
}

// ---------------- launch ----------------
extern "C" void kernel_launch(void* const* d_in, const int* in_sizes, int n_in,
                              void* d_out, int out_size)
{
    const float* x        = (const float*)d_in[0];
    const float* norm1_g  = (const float*)d_in[1];
    const float* norm1_b  = (const float*)d_in[2];
    const float* qkv_w    = (const float*)d_in[3];
    const float* qkv_b    = (const float*)d_in[4];
    const float* bias_tab = (const float*)d_in[5];
    const float* proj_w   = (const float*)d_in[6];
    const float* proj_b   = (const float*)d_in[7];
    const float* norm2_g  = (const float*)d_in[8];
    const float* norm2_b  = (const float*)d_in[9];
    const float* fc1_w    = (const float*)d_in[10];
    const float* fc1_b    = (const float*)d_in[11];
    const float* fc2_w    = (const float*)d_in[12];
    const float* fc2_b    = (const float*)d_in[13];
    float* out = (float*)d_out;

    __half *xw, *qkvb, *attno, *h1, *wq, *wp, *w1, *w2;
    float *x2, *bf;
    cudaGetSymbolAddress((void**)&xw,    g_xw);
    cudaGetSymbolAddress((void**)&qkvb,  g_qkv);
    cudaGetSymbolAddress((void**)&attno, g_attnout);
    cudaGetSymbolAddress((void**)&x2,    g_x2);
    cudaGetSymbolAddress((void**)&h1,    g_h1);
    cudaGetSymbolAddress((void**)&wq,    g_wq);
    cudaGetSymbolAddress((void**)&wp,    g_wp);
    cudaGetSymbolAddress((void**)&w1,    g_w1);
    cudaGetSymbolAddress((void**)&w2,    g_w2);
    cudaGetSymbolAddress((void**)&bf,    g_biasf);

    cudaFuncSetAttribute(attn_mma, cudaFuncAttributeMaxDynamicSharedMemorySize, ATT_SMEM);
    cudaFuncSetAttribute(gemm_t<192,2,4,1>, cudaFuncAttributeMaxDynamicSharedMemorySize, GSMEM192);
    cudaFuncSetAttribute(gemm_t<96,4,2,2>,  cudaFuncAttributeMaxDynamicSharedMemorySize, GSMEM96);

    // merged setup
    setup_kernel<<<(NSETUP+255)/256, 256>>>(qkv_w, proj_w, fc1_w, fc2_w, bias_tab,
                                            wq, wp, w1, w2, bf);

    // 1. LN1 + window partition -> half
    ln_kernel<<<TOKENS/8, 256>>>(x, norm1_g, norm1_b, xw, 1);
    // 2. QKV GEMM -> half (high-occupancy variant)
    gemm_t<96,4,2,2><<<dim3(QKVDIM/96, TOKENS/BM), 256, GSMEM96>>>(xw, wq, qkv_b, qkvb,
        QKVDIM, CC, 0, nullptr, nullptr, nullptr, nullptr);
    // 3. windowed attention -> half
    attn_mma<<<dim3(HEADS, NWIN), 256, ATT_SMEM>>>(qkvb, bf, attno);
    // 4. proj + window-reverse + residual -> x2 (f32), fused LN2 -> xw (half)
    gemm_t<192,2,4,1><<<dim3(CC/192, TOKENS/BM), 256, GSMEM192>>>(attno, wp, proj_b, x2,
        CC, CC, 3, x, norm2_g, norm2_b, xw);
    // 5. FC1 + GELU -> half (high-occupancy variant)
    gemm_t<96,4,2,2><<<dim3(HIDDEN/96, TOKENS/BM), 256, GSMEM96>>>(xw, w1, fc1_b, h1,
        HIDDEN, CC, 1, nullptr, nullptr, nullptr, nullptr);
    // 6. FC2 + residual -> out (f32, high-occupancy variant)
    gemm_t<96,4,2,2><<<dim3(CC/96, TOKENS/BM), 256, GSMEM96>>>(h1, w2, fc2_b, out,
        CC, HIDDEN, 2, x2, nullptr, nullptr, nullptr);
}